// round 1
// baseline (speedup 1.0000x reference)
#include <cuda_runtime.h>
#include <cuda_bf16.h>
#include <cstdint>

// Problem constants
#define BATCH 64
#define SEQ   512
#define DMODEL 256
#define NHEAD 4
#define HDIM  64
#define MTOT  (BATCH * SEQ)          // 32768 rows

// ---------------- scratch (device globals; no allocation allowed) ------------
__device__ float g_Q[MTOT * DMODEL];
__device__ float g_K[MTOT * DMODEL];
__device__ float g_V[MTOT * DMODEL];
__device__ float g_A[MTOT * DMODEL];

// ---------------- GEMM: C[M,N] = A[M,K] @ W[N,K]^T + bias ------------------
// Block tile 128x64, BK=16, 256 threads, per-thread 8x4 microtile.
#define GBM 128
#define GBN 64
#define GBK 16
#define BS_STRIDE 68

__global__ __launch_bounds__(256)
void gemm_bias_kernel(const float* __restrict__ A, const float* __restrict__ W,
                      const float* __restrict__ bias, float* __restrict__ C,
                      int M, int Nn, int K)
{
    __shared__ float As[GBM * GBK];          // [m][k], stride 16
    __shared__ float Bs[GBK * BS_STRIDE];    // [k][n], stride 68 (padded)

    const int tid = threadIdx.x;
    const int m0 = blockIdx.y * GBM;
    const int n0 = blockIdx.x * GBN;
    const int ty = tid >> 4;   // 0..15 -> rows ty*8 .. ty*8+7
    const int tx = tid & 15;   // 0..15 -> cols tx*4 .. tx*4+3

    float acc[8][4];
#pragma unroll
    for (int i = 0; i < 8; i++)
#pragma unroll
        for (int j = 0; j < 4; j++) acc[i][j] = 0.f;

    for (int k0 = 0; k0 < K; k0 += GBK) {
        // Load A tile: 128x16 = 512 float4, 2 per thread (coalesced, cf-free store)
#pragma unroll
        for (int it = 0; it < 2; it++) {
            int lin = it * 256 + tid;
            int r = lin >> 2, kq = lin & 3;
            float4 v = *(const float4*)&A[(size_t)(m0 + r) * K + k0 + kq * 4];
            *(float4*)&As[r * GBK + kq * 4] = v;
        }
        // Load W tile 64x16 = 256 float4, 1 per thread; transpose into Bs[k][n]
        {
            int r = tid >> 2, kq = tid & 3;
            float4 v = *(const float4*)&W[(size_t)(n0 + r) * K + k0 + kq * 4];
            Bs[(kq * 4 + 0) * BS_STRIDE + r] = v.x;
            Bs[(kq * 4 + 1) * BS_STRIDE + r] = v.y;
            Bs[(kq * 4 + 2) * BS_STRIDE + r] = v.z;
            Bs[(kq * 4 + 3) * BS_STRIDE + r] = v.w;
        }
        __syncthreads();

#pragma unroll
        for (int kk = 0; kk < GBK; kk++) {
            float a[8];
#pragma unroll
            for (int i = 0; i < 8; i++) a[i] = As[(ty * 8 + i) * GBK + kk];
            float4 b4 = *(const float4*)&Bs[kk * BS_STRIDE + tx * 4];
#pragma unroll
            for (int i = 0; i < 8; i++) {
                acc[i][0] += a[i] * b4.x;
                acc[i][1] += a[i] * b4.y;
                acc[i][2] += a[i] * b4.z;
                acc[i][3] += a[i] * b4.w;
            }
        }
        __syncthreads();
    }

    float4 bb = *(const float4*)&bias[n0 + tx * 4];
#pragma unroll
    for (int i = 0; i < 8; i++) {
        float4 o = make_float4(acc[i][0] + bb.x, acc[i][1] + bb.y,
                               acc[i][2] + bb.z, acc[i][3] + bb.w);
        *(float4*)&C[(size_t)(m0 + ty * 8 + i) * Nn + n0 + tx * 4] = o;
    }
}

// ---------------- Masked flash attention ------------------------------------
// One block per (query-tile of 64, head, batch). 256 threads.
// smem: Qt [d][q] (transposed), Ks [k][d], Vs [k][d], Ps [k][q], stats.
#define ST 68
#define ATTN_SMEM_FLOATS (4 * 64 * ST + 128)
#define ATTN_SMEM_BYTES  (ATTN_SMEM_FLOATS * 4)

__global__ __launch_bounds__(256)
void attn_kernel(const float* __restrict__ Q, const float* __restrict__ Kb,
                 const float* __restrict__ Vb, const int* __restrict__ adj,
                 float* __restrict__ O)
{
    extern __shared__ float sm[];
    float* Qt = sm;                    // [64 d][ST] -> Qt[d*ST + q]
    float* Ks = Qt + 64 * ST;          // [64 k][ST] -> Ks[k*ST + d]
    float* Vs = Ks + 64 * ST;          // [64 k][ST] -> Vs[k*ST + d]
    float* Ps = Vs + 64 * ST;          // [64 k][ST] -> Ps[k*ST + q]
    float* row_scale = Ps + 64 * ST;   // [64]
    float* row_l     = row_scale + 64; // [64]

    const int tid = threadIdx.x;
    const int q0 = blockIdx.x * 64;
    const int h  = blockIdx.y;
    const int b  = blockIdx.z;
    const int ty = tid >> 4, tx = tid & 15;   // microtile mapping
    const int r  = tid >> 2, c  = tid & 3;    // softmax row mapping (4 thr/row)

    const size_t base = (size_t)b * SEQ * DMODEL + (size_t)h * HDIM;

    // Load Q tile, transpose to Qt[d][q], pre-scale by 1/sqrt(HD)=0.125
#pragma unroll
    for (int it = 0; it < 4; it++) {
        int lin = it * 256 + tid;
        int q = lin >> 4, dq = lin & 15;
        float4 v = *(const float4*)&Q[base + (size_t)(q0 + q) * DMODEL + dq * 4];
        Qt[(dq * 4 + 0) * ST + q] = v.x * 0.125f;
        Qt[(dq * 4 + 1) * ST + q] = v.y * 0.125f;
        Qt[(dq * 4 + 2) * ST + q] = v.z * 0.125f;
        Qt[(dq * 4 + 3) * ST + q] = v.w * 0.125f;
    }

    float m_old = -1e30f, l = 0.f;
    float o[4][4];
#pragma unroll
    for (int i = 0; i < 4; i++)
#pragma unroll
        for (int j = 0; j < 4; j++) o[i][j] = 0.f;

    for (int t = 0; t < SEQ / 64; t++) {
        const int k0 = t * 64;
        __syncthreads();   // prior PV done with Ks/Vs/Ps; Qt ready on first iter

        // Load K,V tiles [64 k][64 d]
#pragma unroll
        for (int it = 0; it < 4; it++) {
            int lin = it * 256 + tid;
            int kk = lin >> 4, dq = lin & 15;
            float4 kv = *(const float4*)&Kb[base + (size_t)(k0 + kk) * DMODEL + dq * 4];
            *(float4*)&Ks[kk * ST + dq * 4] = kv;
            float4 vv = *(const float4*)&Vb[base + (size_t)(k0 + kk) * DMODEL + dq * 4];
            *(float4*)&Vs[kk * ST + dq * 4] = vv;
        }
        __syncthreads();

        // ---- S stage: s[key i][query j], ty->keys, tx->queries -------------
        {
            float s[4][4];
#pragma unroll
            for (int i = 0; i < 4; i++)
#pragma unroll
                for (int j = 0; j < 4; j++) s[i][j] = 0.f;

#pragma unroll
            for (int dq = 0; dq < 16; dq++) {
                float qb[4][4];
#pragma unroll
                for (int u = 0; u < 4; u++) {
                    float4 tq = *(const float4*)&Qt[(dq * 4 + u) * ST + tx * 4];
                    qb[u][0] = tq.x; qb[u][1] = tq.y; qb[u][2] = tq.z; qb[u][3] = tq.w;
                }
#pragma unroll
                for (int i = 0; i < 4; i++) {
                    float4 a = *(const float4*)&Ks[(ty * 4 + i) * ST + dq * 4];
#pragma unroll
                    for (int j = 0; j < 4; j++)
                        s[i][j] += a.x * qb[0][j] + a.y * qb[1][j]
                                 + a.z * qb[2][j] + a.w * qb[3][j];
                }
            }
#pragma unroll
            for (int i = 0; i < 4; i++) {
                float4 sv = make_float4(s[i][0], s[i][1], s[i][2], s[i][3]);
                *(float4*)&Ps[(ty * 4 + i) * ST + tx * 4] = sv;
            }
        }
        __syncthreads();

        // ---- Softmax stage: 4 threads per query row, 16 keys each ----------
        {
            float vals[16];
            float tmax = -1e30f;
#pragma unroll
            for (int kk = 0; kk < 16; kk++) {
                int kloc = c * 16 + kk;
                float sv = Ps[kloc * ST + r];
                int av = adj[(size_t)(q0 + r) * SEQ + k0 + kloc];
                sv = (av != 0) ? sv : -1e30f;
                vals[kk] = sv;
                tmax = fmaxf(tmax, sv);
            }
            tmax = fmaxf(tmax, __shfl_xor_sync(0xffffffffu, tmax, 1));
            tmax = fmaxf(tmax, __shfl_xor_sync(0xffffffffu, tmax, 2));
            float m_new = fmaxf(m_old, tmax);
            float scale = __expf(m_old - m_new);
            float tsum = 0.f;
#pragma unroll
            for (int kk = 0; kk < 16; kk++) {
                int kloc = c * 16 + kk;
                float p = (vals[kk] > -1e29f) ? __expf(vals[kk] - m_new) : 0.f;
                Ps[kloc * ST + r] = p;
                tsum += p;
            }
            tsum += __shfl_xor_sync(0xffffffffu, tsum, 1);
            tsum += __shfl_xor_sync(0xffffffffu, tsum, 2);
            l = l * scale + tsum;
            m_old = m_new;
            if (c == 0) { row_scale[r] = scale; row_l[r] = l; }
        }
        __syncthreads();

        // ---- PV stage: ty->queries, tx->dims; rank-1 stream over keys ------
        {
            float rs[4];
#pragma unroll
            for (int i = 0; i < 4; i++) rs[i] = row_scale[ty * 4 + i];
#pragma unroll
            for (int i = 0; i < 4; i++)
#pragma unroll
                for (int j = 0; j < 4; j++) o[i][j] *= rs[i];

#pragma unroll 16
            for (int k = 0; k < 64; k++) {
                float4 p4 = *(const float4*)&Ps[k * ST + ty * 4];
                float4 v4 = *(const float4*)&Vs[k * ST + tx * 4];
                o[0][0] += p4.x * v4.x; o[0][1] += p4.x * v4.y;
                o[0][2] += p4.x * v4.z; o[0][3] += p4.x * v4.w;
                o[1][0] += p4.y * v4.x; o[1][1] += p4.y * v4.y;
                o[1][2] += p4.y * v4.z; o[1][3] += p4.y * v4.w;
                o[2][0] += p4.z * v4.x; o[2][1] += p4.z * v4.y;
                o[2][2] += p4.z * v4.z; o[2][3] += p4.z * v4.w;
                o[3][0] += p4.w * v4.x; o[3][1] += p4.w * v4.y;
                o[3][2] += p4.w * v4.z; o[3][3] += p4.w * v4.w;
            }
        }
    }

    // ---- finalize: divide by l, write head slice ----------------------------
#pragma unroll
    for (int i = 0; i < 4; i++) {
        float inv = 1.0f / row_l[ty * 4 + i];
        float4 out4 = make_float4(o[i][0] * inv, o[i][1] * inv,
                                  o[i][2] * inv, o[i][3] * inv);
        *(float4*)&O[base + (size_t)(q0 + ty * 4 + i) * DMODEL + tx * 4] = out4;
    }
}

// ---------------- launch -----------------------------------------------------
extern "C" void kernel_launch(void* const* d_in, const int* in_sizes, int n_in,
                              void* d_out, int out_size)
{
    const float* x  = (const float*)d_in[0];
    const int*   adj = (const int*) d_in[1];
    const float* wq = (const float*)d_in[2];
    const float* bq = (const float*)d_in[3];
    const float* wk = (const float*)d_in[4];
    const float* bk = (const float*)d_in[5];
    const float* wv = (const float*)d_in[6];
    const float* bv = (const float*)d_in[7];
    const float* wo = (const float*)d_in[8];
    const float* bo = (const float*)d_in[9];
    float* out = (float*)d_out;

    float *gQ, *gK, *gV, *gA;
    cudaGetSymbolAddress((void**)&gQ, g_Q);
    cudaGetSymbolAddress((void**)&gK, g_K);
    cudaGetSymbolAddress((void**)&gV, g_V);
    cudaGetSymbolAddress((void**)&gA, g_A);

    cudaFuncSetAttribute(attn_kernel,
                         cudaFuncAttributeMaxDynamicSharedMemorySize,
                         ATTN_SMEM_BYTES);

    dim3 ggrid(DMODEL / GBN, MTOT / GBM);   // (4, 256)
    gemm_bias_kernel<<<ggrid, 256>>>(x, wq, bq, gQ, MTOT, DMODEL, DMODEL);
    gemm_bias_kernel<<<ggrid, 256>>>(x, wk, bk, gK, MTOT, DMODEL, DMODEL);
    gemm_bias_kernel<<<ggrid, 256>>>(x, wv, bv, gV, MTOT, DMODEL, DMODEL);

    attn_kernel<<<dim3(SEQ / 64, NHEAD, BATCH), 256, ATTN_SMEM_BYTES>>>(
        gQ, gK, gV, adj, gA);

    gemm_bias_kernel<<<ggrid, 256>>>(gA, wo, bo, out, MTOT, DMODEL, DMODEL);
}

// round 3
// speedup vs baseline: 1.2368x; 1.2368x over previous
#include <cuda_runtime.h>
#include <cuda_bf16.h>
#include <cstdint>

// Problem constants
#define BATCH 64
#define SEQ   512
#define DMODEL 256
#define NHEAD 4
#define HDIM  64
#define MTOT  (BATCH * SEQ)          // 32768 rows

// ---------------- scratch (device globals; no allocation allowed) ------------
__device__ float g_Q[MTOT * DMODEL];
__device__ float g_K[MTOT * DMODEL];
__device__ float g_V[MTOT * DMODEL];
__device__ float g_A[MTOT * DMODEL];
__device__ __nv_bfloat16 g_xh[MTOT * DMODEL];
__device__ __nv_bfloat16 g_xl[MTOT * DMODEL];
__device__ __nv_bfloat16 g_ah[MTOT * DMODEL];
__device__ __nv_bfloat16 g_al[MTOT * DMODEL];
__device__ __nv_bfloat16 g_wh[4 * DMODEL * DMODEL];
__device__ __nv_bfloat16 g_wl[4 * DMODEL * DMODEL];

// ---------------- bf16 two-term split ---------------------------------------
__global__ __launch_bounds__(256)
void split_kernel(const float* __restrict__ in,
                  __nv_bfloat16* __restrict__ hi,
                  __nv_bfloat16* __restrict__ lo, int n4)
{
    int i = blockIdx.x * blockDim.x + threadIdx.x;
    if (i >= n4) return;
    float4 v = ((const float4*)in)[i];
    __nv_bfloat16 h0 = __float2bfloat16(v.x);
    __nv_bfloat16 h1 = __float2bfloat16(v.y);
    __nv_bfloat16 h2 = __float2bfloat16(v.z);
    __nv_bfloat16 h3 = __float2bfloat16(v.w);
    float r0 = v.x - __bfloat162float(h0);
    float r1 = v.y - __bfloat162float(h1);
    float r2 = v.z - __bfloat162float(h2);
    float r3 = v.w - __bfloat162float(h3);
    __nv_bfloat162 h01; h01.x = h0; h01.y = h1;
    __nv_bfloat162 h23; h23.x = h2; h23.y = h3;
    __nv_bfloat162 l01; l01.x = __float2bfloat16(r0); l01.y = __float2bfloat16(r1);
    __nv_bfloat162 l23; l23.x = __float2bfloat16(r2); l23.y = __float2bfloat16(r3);
    ((__nv_bfloat162*)hi)[2*i]     = h01;
    ((__nv_bfloat162*)hi)[2*i + 1] = h23;
    ((__nv_bfloat162*)lo)[2*i]     = l01;
    ((__nv_bfloat162*)lo)[2*i + 1] = l23;
}

// ---------------- mma.sync bf16 GEMM ----------------------------------------
// C[M,256] = (Ah+Al)[M,256] @ (Wh+Wl)[256,256]^T + bias, 3-pass bf16 split.
// Block tile 128x128, 8 warps in 2(m) x 4(n) grid, warp tile 64x32.
// smem tiles [row][k] bf16 with padded stride 72 elems (144B) -> conflict-free
// plain-LDS fragment loads (no ldmatrix needed).
#define SMSTRIDE 72
#define TILE_ELEMS (128 * SMSTRIDE)
#define TILE_BYTES2 (TILE_ELEMS * 2)
#define MG_SMEM (4 * TILE_BYTES2)   // 73728 B

#define MMA_BF16(acc, a, b) \
    asm volatile("mma.sync.aligned.m16n8k16.row.col.f32.bf16.bf16.f32 " \
        "{%0,%1,%2,%3},{%4,%5,%6,%7},{%8,%9},{%0,%1,%2,%3};" \
        : "+f"((acc)[0]), "+f"((acc)[1]), "+f"((acc)[2]), "+f"((acc)[3]) \
        : "r"((a)[0]), "r"((a)[1]), "r"((a)[2]), "r"((a)[3]), \
          "r"((b)[0]), "r"((b)[1]))

__device__ __forceinline__ void load_tile2(__nv_bfloat16* dst,
        const __nv_bfloat16* __restrict__ src, int row0, int kc, int tid)
{
    // 128 rows x 64 k, 16B global loads, 2x8B smem stores (stride 144B)
#pragma unroll
    for (int it = 0; it < 4; it++) {
        int lin = it * 256 + tid;
        int r = lin >> 3, c = lin & 7;
        uint4 v = *(const uint4*)(src + (size_t)(row0 + r) * DMODEL + kc * 64 + c * 8);
        char* d = (char*)dst + r * (SMSTRIDE * 2) + c * 16;
        *(uint2*)d       = make_uint2(v.x, v.y);
        *(uint2*)(d + 8) = make_uint2(v.z, v.w);
    }
}

__global__ __launch_bounds__(256)
void mma_gemm(const __nv_bfloat16* __restrict__ Ah, const __nv_bfloat16* __restrict__ Al,
              const __nv_bfloat16* __restrict__ Bh, const __nv_bfloat16* __restrict__ Bl,
              const float* __restrict__ bias, float* __restrict__ C)
{
    extern __shared__ char sm[];
    __nv_bfloat16* sAh = (__nv_bfloat16*)(sm);
    __nv_bfloat16* sAl = (__nv_bfloat16*)(sm + 1 * TILE_BYTES2);
    __nv_bfloat16* sBh = (__nv_bfloat16*)(sm + 2 * TILE_BYTES2);
    __nv_bfloat16* sBl = (__nv_bfloat16*)(sm + 3 * TILE_BYTES2);

    const int tid  = threadIdx.x;
    const int lane = tid & 31;
    const int warp = tid >> 5;
    const int wm   = warp >> 2;     // 0..1 -> 64 rows
    const int wn   = warp & 3;      // 0..3 -> 32 cols
    const int m0   = blockIdx.y * 128;
    const int n0   = blockIdx.x * 128;

    float acc[4][4][4];
#pragma unroll
    for (int i = 0; i < 4; i++)
#pragma unroll
        for (int j = 0; j < 4; j++)
#pragma unroll
            for (int t = 0; t < 4; t++) acc[i][j][t] = 0.f;

    const int frow = lane >> 2;        // 0..7
    const int fcol = (lane & 3) * 2;   // 0,2,4,6

    for (int kc = 0; kc < 4; kc++) {
        __syncthreads();
        load_tile2(sAh, Ah, m0, kc, tid);
        load_tile2(sAl, Al, m0, kc, tid);
        load_tile2(sBh, Bh, n0, kc, tid);
        load_tile2(sBl, Bl, n0, kc, tid);
        __syncthreads();

#pragma unroll
        for (int ks = 0; ks < 4; ks++) {
            const int kb = ks * 16 + fcol;
            uint32_t ah[4][4], al[4][4];
#pragma unroll
            for (int mi = 0; mi < 4; mi++) {
                int row = wm * 64 + mi * 16 + frow;
                int base = row * SMSTRIDE + kb;
                ah[mi][0] = *(const uint32_t*)&sAh[base];
                ah[mi][1] = *(const uint32_t*)&sAh[base + 8 * SMSTRIDE];
                ah[mi][2] = *(const uint32_t*)&sAh[base + 8];
                ah[mi][3] = *(const uint32_t*)&sAh[base + 8 * SMSTRIDE + 8];
                al[mi][0] = *(const uint32_t*)&sAl[base];
                al[mi][1] = *(const uint32_t*)&sAl[base + 8 * SMSTRIDE];
                al[mi][2] = *(const uint32_t*)&sAl[base + 8];
                al[mi][3] = *(const uint32_t*)&sAl[base + 8 * SMSTRIDE + 8];
            }
            uint32_t bh[4][2], bl[4][2];
#pragma unroll
            for (int ni = 0; ni < 4; ni++) {
                int nrow = wn * 32 + ni * 8 + frow;
                int nb = nrow * SMSTRIDE + kb;
                bh[ni][0] = *(const uint32_t*)&sBh[nb];
                bh[ni][1] = *(const uint32_t*)&sBh[nb + 8];
                bl[ni][0] = *(const uint32_t*)&sBl[nb];
                bl[ni][1] = *(const uint32_t*)&sBl[nb + 8];
            }
#pragma unroll
            for (int mi = 0; mi < 4; mi++)
#pragma unroll
                for (int ni = 0; ni < 4; ni++) {
                    MMA_BF16(acc[mi][ni], ah[mi], bh[ni]);
                    MMA_BF16(acc[mi][ni], ah[mi], bl[ni]);
                    MMA_BF16(acc[mi][ni], al[mi], bh[ni]);
                }
        }
    }

    // epilogue + bias
#pragma unroll
    for (int mi = 0; mi < 4; mi++) {
#pragma unroll
        for (int ni = 0; ni < 4; ni++) {
            int row = m0 + wm * 64 + mi * 16 + frow;
            int col = n0 + wn * 32 + ni * 8 + fcol;
            float b0 = __ldg(&bias[col]);
            float b1 = __ldg(&bias[col + 1]);
            float2 o0 = make_float2(acc[mi][ni][0] + b0, acc[mi][ni][1] + b1);
            float2 o1 = make_float2(acc[mi][ni][2] + b0, acc[mi][ni][3] + b1);
            *(float2*)&C[(size_t)row * DMODEL + col] = o0;
            *(float2*)&C[(size_t)(row + 8) * DMODEL + col] = o1;
        }
    }
}

// ---------------- Masked flash attention (unchanged from R1) -----------------
#define ST 68
#define ATTN_SMEM_FLOATS (4 * 64 * ST + 128)
#define ATTN_SMEM_BYTES  (ATTN_SMEM_FLOATS * 4)

__global__ __launch_bounds__(256)
void attn_kernel(const float* __restrict__ Q, const float* __restrict__ Kb,
                 const float* __restrict__ Vb, const int* __restrict__ adj,
                 float* __restrict__ O)
{
    extern __shared__ float smf[];
    float* Qt = smf;
    float* Ks = Qt + 64 * ST;
    float* Vs = Ks + 64 * ST;
    float* Ps = Vs + 64 * ST;
    float* row_scale = Ps + 64 * ST;
    float* row_l     = row_scale + 64;

    const int tid = threadIdx.x;
    const int q0 = blockIdx.x * 64;
    const int h  = blockIdx.y;
    const int b  = blockIdx.z;
    const int ty = tid >> 4, tx = tid & 15;
    const int r  = tid >> 2, c  = tid & 3;

    const size_t base = (size_t)b * SEQ * DMODEL + (size_t)h * HDIM;

#pragma unroll
    for (int it = 0; it < 4; it++) {
        int lin = it * 256 + tid;
        int q = lin >> 4, dq = lin & 15;
        float4 v = *(const float4*)&Q[base + (size_t)(q0 + q) * DMODEL + dq * 4];
        Qt[(dq * 4 + 0) * ST + q] = v.x * 0.125f;
        Qt[(dq * 4 + 1) * ST + q] = v.y * 0.125f;
        Qt[(dq * 4 + 2) * ST + q] = v.z * 0.125f;
        Qt[(dq * 4 + 3) * ST + q] = v.w * 0.125f;
    }

    float m_old = -1e30f, l = 0.f;
    float o[4][4];
#pragma unroll
    for (int i = 0; i < 4; i++)
#pragma unroll
        for (int j = 0; j < 4; j++) o[i][j] = 0.f;

    for (int t = 0; t < SEQ / 64; t++) {
        const int k0 = t * 64;
        __syncthreads();

#pragma unroll
        for (int it = 0; it < 4; it++) {
            int lin = it * 256 + tid;
            int kk = lin >> 4, dq = lin & 15;
            float4 kv = *(const float4*)&Kb[base + (size_t)(k0 + kk) * DMODEL + dq * 4];
            *(float4*)&Ks[kk * ST + dq * 4] = kv;
            float4 vv = *(const float4*)&Vb[base + (size_t)(k0 + kk) * DMODEL + dq * 4];
            *(float4*)&Vs[kk * ST + dq * 4] = vv;
        }
        __syncthreads();

        {
            float s[4][4];
#pragma unroll
            for (int i = 0; i < 4; i++)
#pragma unroll
                for (int j = 0; j < 4; j++) s[i][j] = 0.f;

#pragma unroll
            for (int dq = 0; dq < 16; dq++) {
                float qb[4][4];
#pragma unroll
                for (int u = 0; u < 4; u++) {
                    float4 tq = *(const float4*)&Qt[(dq * 4 + u) * ST + tx * 4];
                    qb[u][0] = tq.x; qb[u][1] = tq.y; qb[u][2] = tq.z; qb[u][3] = tq.w;
                }
#pragma unroll
                for (int i = 0; i < 4; i++) {
                    float4 a = *(const float4*)&Ks[(ty * 4 + i) * ST + dq * 4];
#pragma unroll
                    for (int j = 0; j < 4; j++)
                        s[i][j] += a.x * qb[0][j] + a.y * qb[1][j]
                                 + a.z * qb[2][j] + a.w * qb[3][j];
                }
            }
#pragma unroll
            for (int i = 0; i < 4; i++) {
                float4 sv = make_float4(s[i][0], s[i][1], s[i][2], s[i][3]);
                *(float4*)&Ps[(ty * 4 + i) * ST + tx * 4] = sv;
            }
        }
        __syncthreads();

        {
            float vals[16];
            float tmax = -1e30f;
#pragma unroll
            for (int kk = 0; kk < 16; kk++) {
                int kloc = c * 16 + kk;
                float sv = Ps[kloc * ST + r];
                int av = adj[(size_t)(q0 + r) * SEQ + k0 + kloc];
                sv = (av != 0) ? sv : -1e30f;
                vals[kk] = sv;
                tmax = fmaxf(tmax, sv);
            }
            tmax = fmaxf(tmax, __shfl_xor_sync(0xffffffffu, tmax, 1));
            tmax = fmaxf(tmax, __shfl_xor_sync(0xffffffffu, tmax, 2));
            float m_new = fmaxf(m_old, tmax);
            float scale = __expf(m_old - m_new);
            float tsum = 0.f;
#pragma unroll
            for (int kk = 0; kk < 16; kk++) {
                int kloc = c * 16 + kk;
                float p = (vals[kk] > -1e29f) ? __expf(vals[kk] - m_new) : 0.f;
                Ps[kloc * ST + r] = p;
                tsum += p;
            }
            tsum += __shfl_xor_sync(0xffffffffu, tsum, 1);
            tsum += __shfl_xor_sync(0xffffffffu, tsum, 2);
            l = l * scale + tsum;
            m_old = m_new;
            if (c == 0) { row_scale[r] = scale; row_l[r] = l; }
        }
        __syncthreads();

        {
            float rs[4];
#pragma unroll
            for (int i = 0; i < 4; i++) rs[i] = row_scale[ty * 4 + i];
#pragma unroll
            for (int i = 0; i < 4; i++)
#pragma unroll
                for (int j = 0; j < 4; j++) o[i][j] *= rs[i];

#pragma unroll 16
            for (int k = 0; k < 64; k++) {
                float4 p4 = *(const float4*)&Ps[k * ST + ty * 4];
                float4 v4 = *(const float4*)&Vs[k * ST + tx * 4];
                o[0][0] += p4.x * v4.x; o[0][1] += p4.x * v4.y;
                o[0][2] += p4.x * v4.z; o[0][3] += p4.x * v4.w;
                o[1][0] += p4.y * v4.x; o[1][1] += p4.y * v4.y;
                o[1][2] += p4.y * v4.z; o[1][3] += p4.y * v4.w;
                o[2][0] += p4.z * v4.x; o[2][1] += p4.z * v4.y;
                o[2][2] += p4.z * v4.z; o[2][3] += p4.z * v4.w;
                o[3][0] += p4.w * v4.x; o[3][1] += p4.w * v4.y;
                o[3][2] += p4.w * v4.z; o[3][3] += p4.w * v4.w;
            }
        }
    }

#pragma unroll
    for (int i = 0; i < 4; i++) {
        float inv = 1.0f / row_l[ty * 4 + i];
        float4 out4 = make_float4(o[i][0] * inv, o[i][1] * inv,
                                  o[i][2] * inv, o[i][3] * inv);
        *(float4*)&O[base + (size_t)(q0 + ty * 4 + i) * DMODEL + tx * 4] = out4;
    }
}

// ---------------- launch -----------------------------------------------------
extern "C" void kernel_launch(void* const* d_in, const int* in_sizes, int n_in,
                              void* d_out, int out_size)
{
    const float* x  = (const float*)d_in[0];
    const int*   adj = (const int*) d_in[1];
    const float* wq = (const float*)d_in[2];
    const float* bq = (const float*)d_in[3];
    const float* wk = (const float*)d_in[4];
    const float* bk = (const float*)d_in[5];
    const float* wv = (const float*)d_in[6];
    const float* bv = (const float*)d_in[7];
    const float* wo = (const float*)d_in[8];
    const float* bo = (const float*)d_in[9];
    float* out = (float*)d_out;

    float *gQ, *gK, *gV, *gA;
    __nv_bfloat16 *gxh, *gxl, *gah, *gal, *gwh, *gwl;
    cudaGetSymbolAddress((void**)&gQ, g_Q);
    cudaGetSymbolAddress((void**)&gK, g_K);
    cudaGetSymbolAddress((void**)&gV, g_V);
    cudaGetSymbolAddress((void**)&gA, g_A);
    cudaGetSymbolAddress((void**)&gxh, g_xh);
    cudaGetSymbolAddress((void**)&gxl, g_xl);
    cudaGetSymbolAddress((void**)&gah, g_ah);
    cudaGetSymbolAddress((void**)&gal, g_al);
    cudaGetSymbolAddress((void**)&gwh, g_wh);
    cudaGetSymbolAddress((void**)&gwl, g_wl);

    cudaFuncSetAttribute(attn_kernel,
                         cudaFuncAttributeMaxDynamicSharedMemorySize,
                         ATTN_SMEM_BYTES);
    cudaFuncSetAttribute(mma_gemm,
                         cudaFuncAttributeMaxDynamicSharedMemorySize,
                         MG_SMEM);

    const int WSZ = DMODEL * DMODEL;           // 65536
    const int n4x = MTOT * DMODEL / 4;         // 2097152
    const int n4w = WSZ / 4;                   // 16384

    split_kernel<<<n4x / 256, 256>>>(x,  gxh, gxl, n4x);
    split_kernel<<<n4w / 256, 256>>>(wq, gwh + 0*WSZ, gwl + 0*WSZ, n4w);
    split_kernel<<<n4w / 256, 256>>>(wk, gwh + 1*WSZ, gwl + 1*WSZ, n4w);
    split_kernel<<<n4w / 256, 256>>>(wv, gwh + 2*WSZ, gwl + 2*WSZ, n4w);
    split_kernel<<<n4w / 256, 256>>>(wo, gwh + 3*WSZ, gwl + 3*WSZ, n4w);

    dim3 ggrid(DMODEL / 128, MTOT / 128);      // (2, 256)
    mma_gemm<<<ggrid, 256, MG_SMEM>>>(gxh, gxl, gwh + 0*WSZ, gwl + 0*WSZ, bq, gQ);
    mma_gemm<<<ggrid, 256, MG_SMEM>>>(gxh, gxl, gwh + 1*WSZ, gwl + 1*WSZ, bk, gK);
    mma_gemm<<<ggrid, 256, MG_SMEM>>>(gxh, gxl, gwh + 2*WSZ, gwl + 2*WSZ, bv, gV);

    attn_kernel<<<dim3(SEQ / 64, NHEAD, BATCH), 256, ATTN_SMEM_BYTES>>>(
        gQ, gK, gV, adj, gA);

    split_kernel<<<n4x / 256, 256>>>(gA, gah, gal, n4x);
    mma_gemm<<<ggrid, 256, MG_SMEM>>>(gah, gal, gwh + 3*WSZ, gwl + 3*WSZ, bo, out);
}

// round 4
// speedup vs baseline: 2.0765x; 1.6789x over previous
#include <cuda_runtime.h>
#include <cuda_bf16.h>
#include <cstdint>

// Problem constants
#define BATCH 64
#define SEQ   512
#define DMODEL 256
#define NHEAD 4
#define HDIM  64
#define MTOT  (BATCH * SEQ)          // 32768 rows

// ---------------- scratch (device globals; no allocation allowed) ------------
__device__ float g_Q[MTOT * DMODEL];
__device__ float g_K[MTOT * DMODEL];
__device__ float g_V[MTOT * DMODEL];
__device__ __nv_bfloat16 g_xh[MTOT * DMODEL];
__device__ __nv_bfloat16 g_xl[MTOT * DMODEL];
__device__ __nv_bfloat16 g_ah[MTOT * DMODEL];
__device__ __nv_bfloat16 g_al[MTOT * DMODEL];
__device__ __nv_bfloat16 g_wh[4 * DMODEL * DMODEL];
__device__ __nv_bfloat16 g_wl[4 * DMODEL * DMODEL];
__device__ uint32_t g_adjbits[SEQ * (SEQ / 32)];   // 512 x 16 words

// ---------------- helpers ----------------------------------------------------
__device__ __forceinline__ uint32_t f2bf2(float hi, float lo) {
    uint32_t r;
    asm("cvt.rn.bf16x2.f32 %0, %1, %2;" : "=r"(r) : "f"(hi), "f"(lo));
    return r;
}
__device__ __forceinline__ float bf_lo(uint32_t u){ return __uint_as_float(u << 16); }
__device__ __forceinline__ float bf_hi(uint32_t u){ return __uint_as_float(u & 0xffff0000u); }

#define MMA_BF16(acc, a, b) \
    asm volatile("mma.sync.aligned.m16n8k16.row.col.f32.bf16.bf16.f32 " \
        "{%0,%1,%2,%3},{%4,%5,%6,%7},{%8,%9},{%0,%1,%2,%3};" \
        : "+f"((acc)[0]), "+f"((acc)[1]), "+f"((acc)[2]), "+f"((acc)[3]) \
        : "r"((a)[0]), "r"((a)[1]), "r"((a)[2]), "r"((a)[3]), \
          "r"((b)[0]), "r"((b)[1]))

// ---------------- bf16 two-term split ---------------------------------------
__global__ __launch_bounds__(256)
void split_kernel(const float* __restrict__ in,
                  __nv_bfloat16* __restrict__ hi,
                  __nv_bfloat16* __restrict__ lo, int n4)
{
    int i = blockIdx.x * blockDim.x + threadIdx.x;
    if (i >= n4) return;
    float4 v = ((const float4*)in)[i];
    uint32_t h01 = f2bf2(v.y, v.x);
    uint32_t h23 = f2bf2(v.w, v.z);
    uint32_t l01 = f2bf2(v.y - bf_hi(h01), v.x - bf_lo(h01));
    uint32_t l23 = f2bf2(v.w - bf_hi(h23), v.z - bf_lo(h23));
    ((uint32_t*)hi)[2*i]     = h01;
    ((uint32_t*)hi)[2*i + 1] = h23;
    ((uint32_t*)lo)[2*i]     = l01;
    ((uint32_t*)lo)[2*i + 1] = l23;
}

// ---------------- adjacency bit-pack -----------------------------------------
__global__ __launch_bounds__(256)
void pack_adj(const int* __restrict__ adj, uint32_t* __restrict__ bits)
{
    int w = blockIdx.x * blockDim.x + threadIdx.x;   // 8192 words
    if (w >= SEQ * (SEQ / 32)) return;
    const int* p = adj + (size_t)w * 32;
    uint32_t m = 0;
#pragma unroll
    for (int i = 0; i < 32; i++) m |= (p[i] != 0 ? 1u : 0u) << i;
    bits[w] = m;
}

// ---------------- mma.sync bf16 GEMM (validated in R3) -----------------------
#define SMSTRIDE 72
#define TILE_ELEMS (128 * SMSTRIDE)
#define TILE_BYTES2 (TILE_ELEMS * 2)
#define MG_SMEM (4 * TILE_BYTES2)   // 73728 B

__device__ __forceinline__ void load_tile2(__nv_bfloat16* dst,
        const __nv_bfloat16* __restrict__ src, int row0, int kc, int tid)
{
#pragma unroll
    for (int it = 0; it < 4; it++) {
        int lin = it * 256 + tid;
        int r = lin >> 3, c = lin & 7;
        uint4 v = *(const uint4*)(src + (size_t)(row0 + r) * DMODEL + kc * 64 + c * 8);
        char* d = (char*)dst + r * (SMSTRIDE * 2) + c * 16;
        *(uint2*)d       = make_uint2(v.x, v.y);
        *(uint2*)(d + 8) = make_uint2(v.z, v.w);
    }
}

__global__ __launch_bounds__(256)
void mma_gemm(const __nv_bfloat16* __restrict__ Ah, const __nv_bfloat16* __restrict__ Al,
              const __nv_bfloat16* __restrict__ Bh, const __nv_bfloat16* __restrict__ Bl,
              const float* __restrict__ bias, float* __restrict__ C)
{
    extern __shared__ char sm[];
    __nv_bfloat16* sAh = (__nv_bfloat16*)(sm);
    __nv_bfloat16* sAl = (__nv_bfloat16*)(sm + 1 * TILE_BYTES2);
    __nv_bfloat16* sBh = (__nv_bfloat16*)(sm + 2 * TILE_BYTES2);
    __nv_bfloat16* sBl = (__nv_bfloat16*)(sm + 3 * TILE_BYTES2);

    const int tid  = threadIdx.x;
    const int lane = tid & 31;
    const int warp = tid >> 5;
    const int wm   = warp >> 2;
    const int wn   = warp & 3;
    const int m0   = blockIdx.y * 128;
    const int n0   = blockIdx.x * 128;

    float acc[4][4][4];
#pragma unroll
    for (int i = 0; i < 4; i++)
#pragma unroll
        for (int j = 0; j < 4; j++)
#pragma unroll
            for (int t = 0; t < 4; t++) acc[i][j][t] = 0.f;

    const int frow = lane >> 2;
    const int fcol = (lane & 3) * 2;

    for (int kc = 0; kc < 4; kc++) {
        __syncthreads();
        load_tile2(sAh, Ah, m0, kc, tid);
        load_tile2(sAl, Al, m0, kc, tid);
        load_tile2(sBh, Bh, n0, kc, tid);
        load_tile2(sBl, Bl, n0, kc, tid);
        __syncthreads();

#pragma unroll
        for (int ks = 0; ks < 4; ks++) {
            const int kb = ks * 16 + fcol;
            uint32_t ah[4][4], al[4][4];
#pragma unroll
            for (int mi = 0; mi < 4; mi++) {
                int row = wm * 64 + mi * 16 + frow;
                int base = row * SMSTRIDE + kb;
                ah[mi][0] = *(const uint32_t*)&sAh[base];
                ah[mi][1] = *(const uint32_t*)&sAh[base + 8 * SMSTRIDE];
                ah[mi][2] = *(const uint32_t*)&sAh[base + 8];
                ah[mi][3] = *(const uint32_t*)&sAh[base + 8 * SMSTRIDE + 8];
                al[mi][0] = *(const uint32_t*)&sAl[base];
                al[mi][1] = *(const uint32_t*)&sAl[base + 8 * SMSTRIDE];
                al[mi][2] = *(const uint32_t*)&sAl[base + 8];
                al[mi][3] = *(const uint32_t*)&sAl[base + 8 * SMSTRIDE + 8];
            }
            uint32_t bh[4][2], bl[4][2];
#pragma unroll
            for (int ni = 0; ni < 4; ni++) {
                int nrow = wn * 32 + ni * 8 + frow;
                int nb = nrow * SMSTRIDE + kb;
                bh[ni][0] = *(const uint32_t*)&sBh[nb];
                bh[ni][1] = *(const uint32_t*)&sBh[nb + 8];
                bl[ni][0] = *(const uint32_t*)&sBl[nb];
                bl[ni][1] = *(const uint32_t*)&sBl[nb + 8];
            }
#pragma unroll
            for (int mi = 0; mi < 4; mi++)
#pragma unroll
                for (int ni = 0; ni < 4; ni++) {
                    MMA_BF16(acc[mi][ni], ah[mi], bh[ni]);
                    MMA_BF16(acc[mi][ni], ah[mi], bl[ni]);
                    MMA_BF16(acc[mi][ni], al[mi], bh[ni]);
                }
        }
    }

#pragma unroll
    for (int mi = 0; mi < 4; mi++) {
#pragma unroll
        for (int ni = 0; ni < 4; ni++) {
            int row = m0 + wm * 64 + mi * 16 + frow;
            int col = n0 + wn * 32 + ni * 8 + fcol;
            float b0 = __ldg(&bias[col]);
            float b1 = __ldg(&bias[col + 1]);
            float2 o0 = make_float2(acc[mi][ni][0] + b0, acc[mi][ni][1] + b1);
            float2 o1 = make_float2(acc[mi][ni][2] + b0, acc[mi][ni][3] + b1);
            *(float2*)&C[(size_t)row * DMODEL + col] = o0;
            *(float2*)&C[(size_t)(row + 8) * DMODEL + col] = o1;
        }
    }
}

// ---------------- mma.sync masked flash attention -----------------------------
// Block: 128 q-rows x (h,b). 8 warps, each warp: 16 q-rows x all 128 keys.
// S and PV both 3-pass bf16 split; P stays in registers (C-frag == A-frag trick).
#define QST 72
#define VST 130
#define OFF_QH 0
#define OFF_QL 18432
#define OFF_KH 36864
#define OFF_KL 55296
#define OFF_VH 73728
#define OFF_VL 90368
#define OFF_MASK 107008
#define ATTN2_SMEM (OFF_MASK + 8192)   // 115200 B

__global__ __launch_bounds__(256)
void attn_mma(const float* __restrict__ Q, const float* __restrict__ K,
              const float* __restrict__ V, const uint32_t* __restrict__ adjbits,
              __nv_bfloat16* __restrict__ Oh, __nv_bfloat16* __restrict__ Ol)
{
    extern __shared__ char sm[];
    __nv_bfloat16* sQh = (__nv_bfloat16*)(sm + OFF_QH);
    __nv_bfloat16* sQl = (__nv_bfloat16*)(sm + OFF_QL);
    __nv_bfloat16* sKh = (__nv_bfloat16*)(sm + OFF_KH);
    __nv_bfloat16* sKl = (__nv_bfloat16*)(sm + OFF_KL);
    __nv_bfloat16* sVh = (__nv_bfloat16*)(sm + OFF_VH);
    __nv_bfloat16* sVl = (__nv_bfloat16*)(sm + OFF_VL);
    uint32_t* maskS = (uint32_t*)(sm + OFF_MASK);

    const int tid = threadIdx.x, lane = tid & 31, warp = tid >> 5;
    const int q0 = blockIdx.x * 128;
    const int h = blockIdx.y, b = blockIdx.z;
    const size_t base = (size_t)b * SEQ * DMODEL + (size_t)h * HDIM;
    const int frow = lane >> 2, fcol = (lane & 3) * 2;

    // Q load + scale + split -> sQh/sQl [row][d] stride QST
#pragma unroll
    for (int it = 0; it < 8; it++) {
        int lin = it * 256 + tid;
        int row = lin >> 4, dq = lin & 15;
        float4 v = *(const float4*)&Q[base + (size_t)(q0 + row) * DMODEL + dq * 4];
        v.x *= 0.125f; v.y *= 0.125f; v.z *= 0.125f; v.w *= 0.125f;
        uint32_t h01 = f2bf2(v.y, v.x), h23 = f2bf2(v.w, v.z);
        uint32_t l01 = f2bf2(v.y - bf_hi(h01), v.x - bf_lo(h01));
        uint32_t l23 = f2bf2(v.w - bf_hi(h23), v.z - bf_lo(h23));
        int o = row * QST + dq * 4;
        *(uint32_t*)&sQh[o] = h01; *(uint32_t*)&sQh[o + 2] = h23;
        *(uint32_t*)&sQl[o] = l01; *(uint32_t*)&sQl[o + 2] = l23;
    }
    // mask tile: 128 rows x 16 words
#pragma unroll
    for (int it = 0; it < 8; it++) {
        int lin = it * 256 + tid;
        int row = lin >> 4, w = lin & 15;
        maskS[row * 16 + w] = adjbits[(size_t)(q0 + row) * 16 + w];
    }

    float m0r = -1e30f, m1r = -1e30f, l0r = 0.f, l1r = 0.f;
    float accO[8][4];
#pragma unroll
    for (int i = 0; i < 8; i++)
#pragma unroll
        for (int j = 0; j < 4; j++) accO[i][j] = 0.f;

    for (int t = 0; t < 4; t++) {
        const int k0 = t * 128;
        __syncthreads();
        // K tile split [key][d]
#pragma unroll
        for (int it = 0; it < 8; it++) {
            int lin = it * 256 + tid;
            int row = lin >> 4, dq = lin & 15;
            float4 v = *(const float4*)&K[base + (size_t)(k0 + row) * DMODEL + dq * 4];
            uint32_t h01 = f2bf2(v.y, v.x), h23 = f2bf2(v.w, v.z);
            uint32_t l01 = f2bf2(v.y - bf_hi(h01), v.x - bf_lo(h01));
            uint32_t l23 = f2bf2(v.w - bf_hi(h23), v.z - bf_lo(h23));
            int o = row * QST + dq * 4;
            *(uint32_t*)&sKh[o] = h01; *(uint32_t*)&sKh[o + 2] = h23;
            *(uint32_t*)&sKl[o] = l01; *(uint32_t*)&sKl[o + 2] = l23;
        }
        // V tile split + transpose -> sVh/sVl [d][key] stride VST
#pragma unroll
        for (int it = 0; it < 8; it++) {
            int lin = it * 256 + tid;
            int key = lin >> 4, dq = lin & 15;
            float4 v = *(const float4*)&V[base + (size_t)(k0 + key) * DMODEL + dq * 4];
            float vv[4] = {v.x, v.y, v.z, v.w};
#pragma unroll
            for (int j = 0; j < 4; j++) {
                int d = dq * 4 + j;
                __nv_bfloat16 vh = __float2bfloat16(vv[j]);
                sVh[d * VST + key] = vh;
                sVl[d * VST + key] = __float2bfloat16(vv[j] - __bfloat162float(vh));
            }
        }
        __syncthreads();

        // ---- S = Q K^T (3-pass split) ----
        float s[16][4];
#pragma unroll
        for (int i = 0; i < 16; i++)
#pragma unroll
            for (int j = 0; j < 4; j++) s[i][j] = 0.f;

#pragma unroll
        for (int ks = 0; ks < 4; ks++) {
            const int kb = ks * 16 + fcol;
            const int ab = (warp * 16 + frow) * QST + kb;
            uint32_t ah[4], al[4];
            ah[0] = *(const uint32_t*)&sQh[ab];
            ah[1] = *(const uint32_t*)&sQh[ab + 8 * QST];
            ah[2] = *(const uint32_t*)&sQh[ab + 8];
            ah[3] = *(const uint32_t*)&sQh[ab + 8 * QST + 8];
            al[0] = *(const uint32_t*)&sQl[ab];
            al[1] = *(const uint32_t*)&sQl[ab + 8 * QST];
            al[2] = *(const uint32_t*)&sQl[ab + 8];
            al[3] = *(const uint32_t*)&sQl[ab + 8 * QST + 8];
#pragma unroll
            for (int ni = 0; ni < 16; ni++) {
                int nb = (ni * 8 + frow) * QST + kb;
                uint32_t bh[2], bl[2];
                bh[0] = *(const uint32_t*)&sKh[nb];
                bh[1] = *(const uint32_t*)&sKh[nb + 8];
                bl[0] = *(const uint32_t*)&sKl[nb];
                bl[1] = *(const uint32_t*)&sKl[nb + 8];
                MMA_BF16(s[ni], ah, bh);
                MMA_BF16(s[ni], ah, bl);
                MMA_BF16(s[ni], al, bh);
            }
        }

        // ---- mask + online softmax (registers + quad shfl) ----
        const int grow = warp * 16 + frow;
        uint4 mw0 = *(const uint4*)&maskS[grow * 16 + t * 4];
        uint4 mw1 = *(const uint4*)&maskS[(grow + 8) * 16 + t * 4];
        const uint32_t* w0p = (const uint32_t*)&mw0;
        const uint32_t* w1p = (const uint32_t*)&mw1;
        float mx0 = -1e30f, mx1 = -1e30f;
#pragma unroll
        for (int ni = 0; ni < 16; ni++) {
            int col = ni * 8 + fcol;
            uint32_t w0 = w0p[ni >> 2], w1 = w1p[ni >> 2];
            if (!((w0 >> (col & 31)) & 1u))       s[ni][0] = -1e30f;
            if (!((w0 >> ((col + 1) & 31)) & 1u)) s[ni][1] = -1e30f;
            if (!((w1 >> (col & 31)) & 1u))       s[ni][2] = -1e30f;
            if (!((w1 >> ((col + 1) & 31)) & 1u)) s[ni][3] = -1e30f;
            mx0 = fmaxf(mx0, fmaxf(s[ni][0], s[ni][1]));
            mx1 = fmaxf(mx1, fmaxf(s[ni][2], s[ni][3]));
        }
        mx0 = fmaxf(mx0, __shfl_xor_sync(0xffffffffu, mx0, 1));
        mx0 = fmaxf(mx0, __shfl_xor_sync(0xffffffffu, mx0, 2));
        mx1 = fmaxf(mx1, __shfl_xor_sync(0xffffffffu, mx1, 1));
        mx1 = fmaxf(mx1, __shfl_xor_sync(0xffffffffu, mx1, 2));
        float mn0 = fmaxf(m0r, mx0), mn1 = fmaxf(m1r, mx1);
        float sc0 = __expf(m0r - mn0), sc1 = __expf(m1r - mn1);
        float ts0 = 0.f, ts1 = 0.f;
#pragma unroll
        for (int ni = 0; ni < 16; ni++) {
            s[ni][0] = __expf(s[ni][0] - mn0);
            s[ni][1] = __expf(s[ni][1] - mn0);
            s[ni][2] = __expf(s[ni][2] - mn1);
            s[ni][3] = __expf(s[ni][3] - mn1);
            ts0 += s[ni][0] + s[ni][1];
            ts1 += s[ni][2] + s[ni][3];
        }
        ts0 += __shfl_xor_sync(0xffffffffu, ts0, 1);
        ts0 += __shfl_xor_sync(0xffffffffu, ts0, 2);
        ts1 += __shfl_xor_sync(0xffffffffu, ts1, 1);
        ts1 += __shfl_xor_sync(0xffffffffu, ts1, 2);
        l0r = l0r * sc0 + ts0;  l1r = l1r * sc1 + ts1;
        m0r = mn0;  m1r = mn1;
#pragma unroll
        for (int ni = 0; ni < 8; ni++) {
            accO[ni][0] *= sc0; accO[ni][1] *= sc0;
            accO[ni][2] *= sc1; accO[ni][3] *= sc1;
        }

        // ---- O += P V (3-pass split; P from registers) ----
#pragma unroll
        for (int kt = 0; kt < 8; kt++) {
            uint32_t pah[4], pal[4];
            pah[0] = f2bf2(s[2*kt][1],   s[2*kt][0]);
            pal[0] = f2bf2(s[2*kt][1]   - bf_hi(pah[0]), s[2*kt][0]   - bf_lo(pah[0]));
            pah[1] = f2bf2(s[2*kt][3],   s[2*kt][2]);
            pal[1] = f2bf2(s[2*kt][3]   - bf_hi(pah[1]), s[2*kt][2]   - bf_lo(pah[1]));
            pah[2] = f2bf2(s[2*kt+1][1], s[2*kt+1][0]);
            pal[2] = f2bf2(s[2*kt+1][1] - bf_hi(pah[2]), s[2*kt+1][0] - bf_lo(pah[2]));
            pah[3] = f2bf2(s[2*kt+1][3], s[2*kt+1][2]);
            pal[3] = f2bf2(s[2*kt+1][3] - bf_hi(pah[3]), s[2*kt+1][2] - bf_lo(pah[3]));
            const int kb = kt * 16 + fcol;
#pragma unroll
            for (int ni = 0; ni < 8; ni++) {
                int nb = (ni * 8 + frow) * VST + kb;
                uint32_t bh[2], bl[2];
                bh[0] = *(const uint32_t*)&sVh[nb];
                bh[1] = *(const uint32_t*)&sVh[nb + 8];
                bl[0] = *(const uint32_t*)&sVl[nb];
                bl[1] = *(const uint32_t*)&sVl[nb + 8];
                MMA_BF16(accO[ni], pah, bh);
                MMA_BF16(accO[ni], pah, bl);
                MMA_BF16(accO[ni], pal, bh);
            }
        }
    }

    // ---- finalize: /l, write bf16 hi/lo directly (feeds out-proj GEMM) ----
    float i0 = 1.f / l0r, i1 = 1.f / l1r;
    const size_t obase = (size_t)b * SEQ * DMODEL;
    const int growg = q0 + warp * 16 + frow;
#pragma unroll
    for (int ni = 0; ni < 8; ni++) {
        int col = h * HDIM + ni * 8 + fcol;
        float o00 = accO[ni][0] * i0, o01 = accO[ni][1] * i0;
        float o10 = accO[ni][2] * i1, o11 = accO[ni][3] * i1;
        uint32_t hh0 = f2bf2(o01, o00);
        uint32_t ll0 = f2bf2(o01 - bf_hi(hh0), o00 - bf_lo(hh0));
        uint32_t hh1 = f2bf2(o11, o10);
        uint32_t ll1 = f2bf2(o11 - bf_hi(hh1), o10 - bf_lo(hh1));
        *(uint32_t*)&Oh[obase + (size_t)growg * DMODEL + col] = hh0;
        *(uint32_t*)&Ol[obase + (size_t)growg * DMODEL + col] = ll0;
        *(uint32_t*)&Oh[obase + (size_t)(growg + 8) * DMODEL + col] = hh1;
        *(uint32_t*)&Ol[obase + (size_t)(growg + 8) * DMODEL + col] = ll1;
    }
}

// ---------------- launch -----------------------------------------------------
extern "C" void kernel_launch(void* const* d_in, const int* in_sizes, int n_in,
                              void* d_out, int out_size)
{
    const float* x  = (const float*)d_in[0];
    const int*   adj = (const int*) d_in[1];
    const float* wq = (const float*)d_in[2];
    const float* bq = (const float*)d_in[3];
    const float* wk = (const float*)d_in[4];
    const float* bk = (const float*)d_in[5];
    const float* wv = (const float*)d_in[6];
    const float* bv = (const float*)d_in[7];
    const float* wo = (const float*)d_in[8];
    const float* bo = (const float*)d_in[9];
    float* out = (float*)d_out;

    float *gQ, *gK, *gV;
    __nv_bfloat16 *gxh, *gxl, *gah, *gal, *gwh, *gwl;
    uint32_t* gab;
    cudaGetSymbolAddress((void**)&gQ, g_Q);
    cudaGetSymbolAddress((void**)&gK, g_K);
    cudaGetSymbolAddress((void**)&gV, g_V);
    cudaGetSymbolAddress((void**)&gxh, g_xh);
    cudaGetSymbolAddress((void**)&gxl, g_xl);
    cudaGetSymbolAddress((void**)&gah, g_ah);
    cudaGetSymbolAddress((void**)&gal, g_al);
    cudaGetSymbolAddress((void**)&gwh, g_wh);
    cudaGetSymbolAddress((void**)&gwl, g_wl);
    cudaGetSymbolAddress((void**)&gab, g_adjbits);

    cudaFuncSetAttribute(mma_gemm,
                         cudaFuncAttributeMaxDynamicSharedMemorySize, MG_SMEM);
    cudaFuncSetAttribute(attn_mma,
                         cudaFuncAttributeMaxDynamicSharedMemorySize, ATTN2_SMEM);

    const int WSZ = DMODEL * DMODEL;           // 65536
    const int n4x = MTOT * DMODEL / 4;         // 2097152
    const int n4w = WSZ / 4;                   // 16384

    split_kernel<<<n4x / 256, 256>>>(x,  gxh, gxl, n4x);
    split_kernel<<<n4w / 256, 256>>>(wq, gwh + 0*WSZ, gwl + 0*WSZ, n4w);
    split_kernel<<<n4w / 256, 256>>>(wk, gwh + 1*WSZ, gwl + 1*WSZ, n4w);
    split_kernel<<<n4w / 256, 256>>>(wv, gwh + 2*WSZ, gwl + 2*WSZ, n4w);
    split_kernel<<<n4w / 256, 256>>>(wo, gwh + 3*WSZ, gwl + 3*WSZ, n4w);
    pack_adj<<<SEQ * (SEQ/32) / 256, 256>>>(adj, gab);

    dim3 ggrid(DMODEL / 128, MTOT / 128);      // (2, 256)
    mma_gemm<<<ggrid, 256, MG_SMEM>>>(gxh, gxl, gwh + 0*WSZ, gwl + 0*WSZ, bq, gQ);
    mma_gemm<<<ggrid, 256, MG_SMEM>>>(gxh, gxl, gwh + 1*WSZ, gwl + 1*WSZ, bk, gK);
    mma_gemm<<<ggrid, 256, MG_SMEM>>>(gxh, gxl, gwh + 2*WSZ, gwl + 2*WSZ, bv, gV);

    attn_mma<<<dim3(SEQ / 128, NHEAD, BATCH), 256, ATTN2_SMEM>>>(
        gQ, gK, gV, gab, gah, gal);

    mma_gemm<<<ggrid, 256, MG_SMEM>>>(gah, gal, gwh + 3*WSZ, gwl + 3*WSZ, bo, out);
}

// round 5
// speedup vs baseline: 2.3298x; 1.1219x over previous
#include <cuda_runtime.h>
#include <cuda_bf16.h>
#include <cstdint>

// Problem constants
#define BATCH 64
#define SEQ   512
#define DMODEL 256
#define NHEAD 4
#define HDIM  64
#define MTOT  (BATCH * SEQ)          // 32768 rows
#define DQKV  768

// ---------------- scratch (device globals; no allocation allowed) ------------
__device__ float g_QKV[MTOT * DQKV];               // fused Q|K|V, fp32
__device__ __nv_bfloat16 g_xh[MTOT * DMODEL];
__device__ __nv_bfloat16 g_xl[MTOT * DMODEL];
__device__ __nv_bfloat16 g_ah[MTOT * DMODEL];
__device__ __nv_bfloat16 g_al[MTOT * DMODEL];
__device__ __nv_bfloat16 g_wh[4 * DMODEL * DMODEL];  // wq|wk|wv|wo stacked
__device__ __nv_bfloat16 g_wl[4 * DMODEL * DMODEL];
__device__ uint32_t g_adjbits[SEQ * (SEQ / 32)];   // 512 x 16 words

// ---------------- helpers ----------------------------------------------------
__device__ __forceinline__ uint32_t f2bf2(float hi, float lo) {
    uint32_t r;
    asm("cvt.rn.bf16x2.f32 %0, %1, %2;" : "=r"(r) : "f"(hi), "f"(lo));
    return r;
}
__device__ __forceinline__ float bf_lo(uint32_t u){ return __uint_as_float(u << 16); }
__device__ __forceinline__ float bf_hi(uint32_t u){ return __uint_as_float(u & 0xffff0000u); }

__device__ __forceinline__ uint32_t s2u(const void* p){
    uint32_t a;
    asm("{ .reg .u64 t; cvta.to.shared.u64 t, %1; cvt.u32.u64 %0, t; }"
        : "=r"(a) : "l"(p));
    return a;
}
__device__ __forceinline__ void cp8(uint32_t dst, const void* src){
    asm volatile("cp.async.ca.shared.global [%0], [%1], 8;" :: "r"(dst), "l"(src));
}

#define MMA_BF16(acc, a, b) \
    asm volatile("mma.sync.aligned.m16n8k16.row.col.f32.bf16.bf16.f32 " \
        "{%0,%1,%2,%3},{%4,%5,%6,%7},{%8,%9},{%0,%1,%2,%3};" \
        : "+f"((acc)[0]), "+f"((acc)[1]), "+f"((acc)[2]), "+f"((acc)[3]) \
        : "r"((a)[0]), "r"((a)[1]), "r"((a)[2]), "r"((a)[3]), \
          "r"((b)[0]), "r"((b)[1]))

// ---------------- bf16 two-term split ---------------------------------------
__global__ __launch_bounds__(256)
void split_kernel(const float* __restrict__ in,
                  __nv_bfloat16* __restrict__ hi,
                  __nv_bfloat16* __restrict__ lo, int n4)
{
    int i = blockIdx.x * blockDim.x + threadIdx.x;
    if (i >= n4) return;
    float4 v = ((const float4*)in)[i];
    uint32_t h01 = f2bf2(v.y, v.x);
    uint32_t h23 = f2bf2(v.w, v.z);
    uint32_t l01 = f2bf2(v.y - bf_hi(h01), v.x - bf_lo(h01));
    uint32_t l23 = f2bf2(v.w - bf_hi(h23), v.z - bf_lo(h23));
    ((uint32_t*)hi)[2*i]     = h01;
    ((uint32_t*)hi)[2*i + 1] = h23;
    ((uint32_t*)lo)[2*i]     = l01;
    ((uint32_t*)lo)[2*i + 1] = l23;
}

// 4 weight matrices in one launch (blockIdx.y selects)
__global__ __launch_bounds__(256)
void split_w(const float* __restrict__ w0, const float* __restrict__ w1,
             const float* __restrict__ w2, const float* __restrict__ w3,
             __nv_bfloat16* __restrict__ hi, __nv_bfloat16* __restrict__ lo)
{
    const int ws = blockIdx.y;
    const float* src = ws == 0 ? w0 : ws == 1 ? w1 : ws == 2 ? w2 : w3;
    const int off4 = ws * (DMODEL * DMODEL / 4);
    int i = blockIdx.x * blockDim.x + threadIdx.x;   // 0..16383
    float4 v = ((const float4*)src)[i];
    uint32_t h01 = f2bf2(v.y, v.x);
    uint32_t h23 = f2bf2(v.w, v.z);
    uint32_t l01 = f2bf2(v.y - bf_hi(h01), v.x - bf_lo(h01));
    uint32_t l23 = f2bf2(v.w - bf_hi(h23), v.z - bf_lo(h23));
    ((uint32_t*)hi)[2*(off4+i)]     = h01;
    ((uint32_t*)hi)[2*(off4+i) + 1] = h23;
    ((uint32_t*)lo)[2*(off4+i)]     = l01;
    ((uint32_t*)lo)[2*(off4+i) + 1] = l23;
}

// ---------------- adjacency bit-pack -----------------------------------------
__global__ __launch_bounds__(256)
void pack_adj(const int* __restrict__ adj, uint32_t* __restrict__ bits)
{
    int w = blockIdx.x * blockDim.x + threadIdx.x;
    if (w >= SEQ * (SEQ / 32)) return;
    const int* p = adj + (size_t)w * 32;
    uint32_t m = 0;
#pragma unroll
    for (int i = 0; i < 32; i++) m |= (p[i] != 0 ? 1u : 0u) << i;
    bits[w] = m;
}

// ---------------- cp.async pipelined mma.sync bf16 GEMM ----------------------
// C[M,Nn] = (Ah+Al)[M,256] @ (Wh+Wl)[Nn,256]^T + bias, 3-pass bf16 split.
// Block 128x128, 8 warps 2x4, warp 64x32. 2-stage cp.async smem pipeline.
#define SMSTRIDE 72
#define TILE_BYTES2 (128 * SMSTRIDE * 2)     // 18432
#define STAGE_B (4 * TILE_BYTES2)            // 73728
#define PIPE_SMEM (2 * STAGE_B)              // 147456

__device__ __forceinline__ void cp_tile(uint32_t smdst,
        const __nv_bfloat16* __restrict__ src, int row0, int kc, int tid)
{
#pragma unroll
    for (int it = 0; it < 4; it++) {
        int lin = it * 256 + tid;
        int r = lin >> 3, c = lin & 7;
        const char* g = (const char*)(src + (size_t)(row0 + r) * DMODEL + kc * 64) + c * 16;
        uint32_t d = smdst + r * (SMSTRIDE * 2) + c * 16;
        cp8(d, g);
        cp8(d + 8, g + 8);
    }
}

__global__ __launch_bounds__(256)
void mma_gemm(const __nv_bfloat16* __restrict__ Ah, const __nv_bfloat16* __restrict__ Al,
              const __nv_bfloat16* __restrict__ Bh, const __nv_bfloat16* __restrict__ Bl,
              const float* __restrict__ b0, const float* __restrict__ b1,
              const float* __restrict__ b2, float* __restrict__ C, int Nn)
{
    extern __shared__ char sm[];
    const uint32_t smb = s2u(sm);

    const int tid  = threadIdx.x;
    const int lane = tid & 31;
    const int warp = tid >> 5;
    const int wm   = warp >> 2;
    const int wn   = warp & 3;
    const int m0   = blockIdx.y * 128;
    const int n0   = blockIdx.x * 128;

    float acc[4][4][4];
#pragma unroll
    for (int i = 0; i < 4; i++)
#pragma unroll
        for (int j = 0; j < 4; j++)
#pragma unroll
            for (int t = 0; t < 4; t++) acc[i][j][t] = 0.f;

    const int frow = lane >> 2;
    const int fcol = (lane & 3) * 2;

    // prologue: chunk 0 -> stage 0
    cp_tile(smb + 0 * TILE_BYTES2, Ah, m0, 0, tid);
    cp_tile(smb + 1 * TILE_BYTES2, Al, m0, 0, tid);
    cp_tile(smb + 2 * TILE_BYTES2, Bh, n0, 0, tid);
    cp_tile(smb + 3 * TILE_BYTES2, Bl, n0, 0, tid);
    asm volatile("cp.async.commit_group;");

#pragma unroll
    for (int kc = 0; kc < 4; kc++) {
        __syncthreads();   // prior compute done everywhere before refilling
        if (kc < 3) {
            uint32_t st = smb + ((kc + 1) & 1) * STAGE_B;
            cp_tile(st + 0 * TILE_BYTES2, Ah, m0, kc + 1, tid);
            cp_tile(st + 1 * TILE_BYTES2, Al, m0, kc + 1, tid);
            cp_tile(st + 2 * TILE_BYTES2, Bh, n0, kc + 1, tid);
            cp_tile(st + 3 * TILE_BYTES2, Bl, n0, kc + 1, tid);
            asm volatile("cp.async.commit_group;");
            asm volatile("cp.async.wait_group 1;");
        } else {
            asm volatile("cp.async.wait_group 0;");
        }
        __syncthreads();

        const char* stc = sm + (kc & 1) * STAGE_B;
        const __nv_bfloat16* sAh = (const __nv_bfloat16*)(stc);
        const __nv_bfloat16* sAl = (const __nv_bfloat16*)(stc + 1 * TILE_BYTES2);
        const __nv_bfloat16* sBh = (const __nv_bfloat16*)(stc + 2 * TILE_BYTES2);
        const __nv_bfloat16* sBl = (const __nv_bfloat16*)(stc + 3 * TILE_BYTES2);

#pragma unroll
        for (int ks = 0; ks < 4; ks++) {
            const int kb = ks * 16 + fcol;
            uint32_t ah[4][4], al[4][4];
#pragma unroll
            for (int mi = 0; mi < 4; mi++) {
                int row = wm * 64 + mi * 16 + frow;
                int base = row * SMSTRIDE + kb;
                ah[mi][0] = *(const uint32_t*)&sAh[base];
                ah[mi][1] = *(const uint32_t*)&sAh[base + 8 * SMSTRIDE];
                ah[mi][2] = *(const uint32_t*)&sAh[base + 8];
                ah[mi][3] = *(const uint32_t*)&sAh[base + 8 * SMSTRIDE + 8];
                al[mi][0] = *(const uint32_t*)&sAl[base];
                al[mi][1] = *(const uint32_t*)&sAl[base + 8 * SMSTRIDE];
                al[mi][2] = *(const uint32_t*)&sAl[base + 8];
                al[mi][3] = *(const uint32_t*)&sAl[base + 8 * SMSTRIDE + 8];
            }
            uint32_t bh[4][2], bl[4][2];
#pragma unroll
            for (int ni = 0; ni < 4; ni++) {
                int nrow = wn * 32 + ni * 8 + frow;
                int nb = nrow * SMSTRIDE + kb;
                bh[ni][0] = *(const uint32_t*)&sBh[nb];
                bh[ni][1] = *(const uint32_t*)&sBh[nb + 8];
                bl[ni][0] = *(const uint32_t*)&sBl[nb];
                bl[ni][1] = *(const uint32_t*)&sBl[nb + 8];
            }
#pragma unroll
            for (int mi = 0; mi < 4; mi++)
#pragma unroll
                for (int ni = 0; ni < 4; ni++) {
                    MMA_BF16(acc[mi][ni], ah[mi], bh[ni]);
                    MMA_BF16(acc[mi][ni], ah[mi], bl[ni]);
                    MMA_BF16(acc[mi][ni], al[mi], bh[ni]);
                }
        }
    }

    // epilogue + bias (region: which of up-to-3 concatenated outputs)
    const int reg = n0 >> 8;
    const float* bp = reg == 0 ? b0 : (reg == 1 ? b1 : b2);
    const int coff = reg << 8;
#pragma unroll
    for (int mi = 0; mi < 4; mi++) {
#pragma unroll
        for (int ni = 0; ni < 4; ni++) {
            int row = m0 + wm * 64 + mi * 16 + frow;
            int col = n0 + wn * 32 + ni * 8 + fcol;
            float bb0 = __ldg(&bp[col - coff]);
            float bb1 = __ldg(&bp[col - coff + 1]);
            float2 o0 = make_float2(acc[mi][ni][0] + bb0, acc[mi][ni][1] + bb1);
            float2 o1 = make_float2(acc[mi][ni][2] + bb0, acc[mi][ni][3] + bb1);
            *(float2*)&C[(size_t)row * Nn + col] = o0;
            *(float2*)&C[(size_t)(row + 8) * Nn + col] = o1;
        }
    }
}

// ---------------- mma.sync masked flash attention -----------------------------
// Reads fused QKV [M,768]; Q at +0, K at +256, V at +512.
#define QST 72
#define VST 130
#define OFF_QH 0
#define OFF_QL 18432
#define OFF_KH 36864
#define OFF_KL 55296
#define OFF_VH 73728
#define OFF_VL 90368
#define OFF_MASK 107008
#define ATTN2_SMEM (OFF_MASK + 8192)   // 115200 B

__global__ __launch_bounds__(256)
void attn_mma(const float* __restrict__ QKV, const uint32_t* __restrict__ adjbits,
              __nv_bfloat16* __restrict__ Oh, __nv_bfloat16* __restrict__ Ol)
{
    extern __shared__ char sm[];
    __nv_bfloat16* sQh = (__nv_bfloat16*)(sm + OFF_QH);
    __nv_bfloat16* sQl = (__nv_bfloat16*)(sm + OFF_QL);
    __nv_bfloat16* sKh = (__nv_bfloat16*)(sm + OFF_KH);
    __nv_bfloat16* sKl = (__nv_bfloat16*)(sm + OFF_KL);
    __nv_bfloat16* sVh = (__nv_bfloat16*)(sm + OFF_VH);
    __nv_bfloat16* sVl = (__nv_bfloat16*)(sm + OFF_VL);
    uint32_t* maskS = (uint32_t*)(sm + OFF_MASK);

    const int tid = threadIdx.x, lane = tid & 31, warp = tid >> 5;
    const int q0 = blockIdx.x * 128;
    const int h = blockIdx.y, b = blockIdx.z;
    const size_t base = (size_t)b * SEQ * DQKV + (size_t)h * HDIM;
    const int frow = lane >> 2, fcol = (lane & 3) * 2;

#pragma unroll
    for (int it = 0; it < 8; it++) {
        int lin = it * 256 + tid;
        int row = lin >> 4, dq = lin & 15;
        float4 v = *(const float4*)&QKV[base + (size_t)(q0 + row) * DQKV + dq * 4];
        v.x *= 0.125f; v.y *= 0.125f; v.z *= 0.125f; v.w *= 0.125f;
        uint32_t h01 = f2bf2(v.y, v.x), h23 = f2bf2(v.w, v.z);
        uint32_t l01 = f2bf2(v.y - bf_hi(h01), v.x - bf_lo(h01));
        uint32_t l23 = f2bf2(v.w - bf_hi(h23), v.z - bf_lo(h23));
        int o = row * QST + dq * 4;
        *(uint32_t*)&sQh[o] = h01; *(uint32_t*)&sQh[o + 2] = h23;
        *(uint32_t*)&sQl[o] = l01; *(uint32_t*)&sQl[o + 2] = l23;
    }
#pragma unroll
    for (int it = 0; it < 8; it++) {
        int lin = it * 256 + tid;
        int row = lin >> 4, w = lin & 15;
        maskS[row * 16 + w] = adjbits[(size_t)(q0 + row) * 16 + w];
    }

    float m0r = -1e30f, m1r = -1e30f, l0r = 0.f, l1r = 0.f;
    float accO[8][4];
#pragma unroll
    for (int i = 0; i < 8; i++)
#pragma unroll
        for (int j = 0; j < 4; j++) accO[i][j] = 0.f;

    for (int t = 0; t < 4; t++) {
        const int k0 = t * 128;
        __syncthreads();
#pragma unroll
        for (int it = 0; it < 8; it++) {
            int lin = it * 256 + tid;
            int row = lin >> 4, dq = lin & 15;
            float4 v = *(const float4*)&QKV[base + (size_t)(k0 + row) * DQKV + 256 + dq * 4];
            uint32_t h01 = f2bf2(v.y, v.x), h23 = f2bf2(v.w, v.z);
            uint32_t l01 = f2bf2(v.y - bf_hi(h01), v.x - bf_lo(h01));
            uint32_t l23 = f2bf2(v.w - bf_hi(h23), v.z - bf_lo(h23));
            int o = row * QST + dq * 4;
            *(uint32_t*)&sKh[o] = h01; *(uint32_t*)&sKh[o + 2] = h23;
            *(uint32_t*)&sKl[o] = l01; *(uint32_t*)&sKl[o + 2] = l23;
        }
#pragma unroll
        for (int it = 0; it < 8; it++) {
            int lin = it * 256 + tid;
            int key = lin >> 4, dq = lin & 15;
            float4 v = *(const float4*)&QKV[base + (size_t)(k0 + key) * DQKV + 512 + dq * 4];
            float vv[4] = {v.x, v.y, v.z, v.w};
#pragma unroll
            for (int j = 0; j < 4; j++) {
                int d = dq * 4 + j;
                __nv_bfloat16 vh = __float2bfloat16(vv[j]);
                sVh[d * VST + key] = vh;
                sVl[d * VST + key] = __float2bfloat16(vv[j] - __bfloat162float(vh));
            }
        }
        __syncthreads();

        float s[16][4];
#pragma unroll
        for (int i = 0; i < 16; i++)
#pragma unroll
            for (int j = 0; j < 4; j++) s[i][j] = 0.f;

#pragma unroll
        for (int ks = 0; ks < 4; ks++) {
            const int kb = ks * 16 + fcol;
            const int ab = (warp * 16 + frow) * QST + kb;
            uint32_t ah[4], al[4];
            ah[0] = *(const uint32_t*)&sQh[ab];
            ah[1] = *(const uint32_t*)&sQh[ab + 8 * QST];
            ah[2] = *(const uint32_t*)&sQh[ab + 8];
            ah[3] = *(const uint32_t*)&sQh[ab + 8 * QST + 8];
            al[0] = *(const uint32_t*)&sQl[ab];
            al[1] = *(const uint32_t*)&sQl[ab + 8 * QST];
            al[2] = *(const uint32_t*)&sQl[ab + 8];
            al[3] = *(const uint32_t*)&sQl[ab + 8 * QST + 8];
#pragma unroll
            for (int ni = 0; ni < 16; ni++) {
                int nb = (ni * 8 + frow) * QST + kb;
                uint32_t bh[2], bl[2];
                bh[0] = *(const uint32_t*)&sKh[nb];
                bh[1] = *(const uint32_t*)&sKh[nb + 8];
                bl[0] = *(const uint32_t*)&sKl[nb];
                bl[1] = *(const uint32_t*)&sKl[nb + 8];
                MMA_BF16(s[ni], ah, bh);
                MMA_BF16(s[ni], ah, bl);
                MMA_BF16(s[ni], al, bh);
            }
        }

        const int grow = warp * 16 + frow;
        uint4 mw0 = *(const uint4*)&maskS[grow * 16 + t * 4];
        uint4 mw1 = *(const uint4*)&maskS[(grow + 8) * 16 + t * 4];
        const uint32_t* w0p = (const uint32_t*)&mw0;
        const uint32_t* w1p = (const uint32_t*)&mw1;
        float mx0 = -1e30f, mx1 = -1e30f;
#pragma unroll
        for (int ni = 0; ni < 16; ni++) {
            int col = ni * 8 + fcol;
            uint32_t w0 = w0p[ni >> 2], w1 = w1p[ni >> 2];
            if (!((w0 >> (col & 31)) & 1u))       s[ni][0] = -1e30f;
            if (!((w0 >> ((col + 1) & 31)) & 1u)) s[ni][1] = -1e30f;
            if (!((w1 >> (col & 31)) & 1u))       s[ni][2] = -1e30f;
            if (!((w1 >> ((col + 1) & 31)) & 1u)) s[ni][3] = -1e30f;
            mx0 = fmaxf(mx0, fmaxf(s[ni][0], s[ni][1]));
            mx1 = fmaxf(mx1, fmaxf(s[ni][2], s[ni][3]));
        }
        mx0 = fmaxf(mx0, __shfl_xor_sync(0xffffffffu, mx0, 1));
        mx0 = fmaxf(mx0, __shfl_xor_sync(0xffffffffu, mx0, 2));
        mx1 = fmaxf(mx1, __shfl_xor_sync(0xffffffffu, mx1, 1));
        mx1 = fmaxf(mx1, __shfl_xor_sync(0xffffffffu, mx1, 2));
        float mn0 = fmaxf(m0r, mx0), mn1 = fmaxf(m1r, mx1);
        float sc0 = __expf(m0r - mn0), sc1 = __expf(m1r - mn1);
        float ts0 = 0.f, ts1 = 0.f;
#pragma unroll
        for (int ni = 0; ni < 16; ni++) {
            s[ni][0] = __expf(s[ni][0] - mn0);
            s[ni][1] = __expf(s[ni][1] - mn0);
            s[ni][2] = __expf(s[ni][2] - mn1);
            s[ni][3] = __expf(s[ni][3] - mn1);
            ts0 += s[ni][0] + s[ni][1];
            ts1 += s[ni][2] + s[ni][3];
        }
        ts0 += __shfl_xor_sync(0xffffffffu, ts0, 1);
        ts0 += __shfl_xor_sync(0xffffffffu, ts0, 2);
        ts1 += __shfl_xor_sync(0xffffffffu, ts1, 1);
        ts1 += __shfl_xor_sync(0xffffffffu, ts1, 2);
        l0r = l0r * sc0 + ts0;  l1r = l1r * sc1 + ts1;
        m0r = mn0;  m1r = mn1;
#pragma unroll
        for (int ni = 0; ni < 8; ni++) {
            accO[ni][0] *= sc0; accO[ni][1] *= sc0;
            accO[ni][2] *= sc1; accO[ni][3] *= sc1;
        }

#pragma unroll
        for (int kt = 0; kt < 8; kt++) {
            uint32_t pah[4], pal[4];
            pah[0] = f2bf2(s[2*kt][1],   s[2*kt][0]);
            pal[0] = f2bf2(s[2*kt][1]   - bf_hi(pah[0]), s[2*kt][0]   - bf_lo(pah[0]));
            pah[1] = f2bf2(s[2*kt][3],   s[2*kt][2]);
            pal[1] = f2bf2(s[2*kt][3]   - bf_hi(pah[1]), s[2*kt][2]   - bf_lo(pah[1]));
            pah[2] = f2bf2(s[2*kt+1][1], s[2*kt+1][0]);
            pal[2] = f2bf2(s[2*kt+1][1] - bf_hi(pah[2]), s[2*kt+1][0] - bf_lo(pah[2]));
            pah[3] = f2bf2(s[2*kt+1][3], s[2*kt+1][2]);
            pal[3] = f2bf2(s[2*kt+1][3] - bf_hi(pah[3]), s[2*kt+1][2] - bf_lo(pah[3]));
            const int kb = kt * 16 + fcol;
#pragma unroll
            for (int ni = 0; ni < 8; ni++) {
                int nb = (ni * 8 + frow) * VST + kb;
                uint32_t bh[2], bl[2];
                bh[0] = *(const uint32_t*)&sVh[nb];
                bh[1] = *(const uint32_t*)&sVh[nb + 8];
                bl[0] = *(const uint32_t*)&sVl[nb];
                bl[1] = *(const uint32_t*)&sVl[nb + 8];
                MMA_BF16(accO[ni], pah, bh);
                MMA_BF16(accO[ni], pah, bl);
                MMA_BF16(accO[ni], pal, bh);
            }
        }
    }

    float i0 = 1.f / l0r, i1 = 1.f / l1r;
    const size_t obase = (size_t)b * SEQ * DMODEL;
    const int growg = q0 + warp * 16 + frow;
#pragma unroll
    for (int ni = 0; ni < 8; ni++) {
        int col = h * HDIM + ni * 8 + fcol;
        float o00 = accO[ni][0] * i0, o01 = accO[ni][1] * i0;
        float o10 = accO[ni][2] * i1, o11 = accO[ni][3] * i1;
        uint32_t hh0 = f2bf2(o01, o00);
        uint32_t ll0 = f2bf2(o01 - bf_hi(hh0), o00 - bf_lo(hh0));
        uint32_t hh1 = f2bf2(o11, o10);
        uint32_t ll1 = f2bf2(o11 - bf_hi(hh1), o10 - bf_lo(hh1));
        *(uint32_t*)&Oh[obase + (size_t)growg * DMODEL + col] = hh0;
        *(uint32_t*)&Ol[obase + (size_t)growg * DMODEL + col] = ll0;
        *(uint32_t*)&Oh[obase + (size_t)(growg + 8) * DMODEL + col] = hh1;
        *(uint32_t*)&Ol[obase + (size_t)(growg + 8) * DMODEL + col] = ll1;
    }
}

// ---------------- launch -----------------------------------------------------
extern "C" void kernel_launch(void* const* d_in, const int* in_sizes, int n_in,
                              void* d_out, int out_size)
{
    const float* x  = (const float*)d_in[0];
    const int*   adj = (const int*) d_in[1];
    const float* wq = (const float*)d_in[2];
    const float* bq = (const float*)d_in[3];
    const float* wk = (const float*)d_in[4];
    const float* bk = (const float*)d_in[5];
    const float* wv = (const float*)d_in[6];
    const float* bv = (const float*)d_in[7];
    const float* wo = (const float*)d_in[8];
    const float* bo = (const float*)d_in[9];
    float* out = (float*)d_out;

    float* gQKV;
    __nv_bfloat16 *gxh, *gxl, *gah, *gal, *gwh, *gwl;
    uint32_t* gab;
    cudaGetSymbolAddress((void**)&gQKV, g_QKV);
    cudaGetSymbolAddress((void**)&gxh, g_xh);
    cudaGetSymbolAddress((void**)&gxl, g_xl);
    cudaGetSymbolAddress((void**)&gah, g_ah);
    cudaGetSymbolAddress((void**)&gal, g_al);
    cudaGetSymbolAddress((void**)&gwh, g_wh);
    cudaGetSymbolAddress((void**)&gwl, g_wl);
    cudaGetSymbolAddress((void**)&gab, g_adjbits);

    cudaFuncSetAttribute(mma_gemm,
                         cudaFuncAttributeMaxDynamicSharedMemorySize, PIPE_SMEM);
    cudaFuncSetAttribute(attn_mma,
                         cudaFuncAttributeMaxDynamicSharedMemorySize, ATTN2_SMEM);

    const int WSZ = DMODEL * DMODEL;           // 65536
    const int n4x = MTOT * DMODEL / 4;         // 2097152

    split_kernel<<<n4x / 256, 256>>>(x, gxh, gxl, n4x);
    split_w<<<dim3(WSZ / 4 / 256, 4), 256>>>(wq, wk, wv, wo, gwh, gwl);
    pack_adj<<<SEQ * (SEQ/32) / 256, 256>>>(adj, gab);

    // fused QKV projection: C[M,768] = x @ [Wq;Wk;Wv]^T + [bq;bk;bv]
    mma_gemm<<<dim3(DQKV / 128, MTOT / 128), 256, PIPE_SMEM>>>(
        gxh, gxl, gwh, gwl, bq, bk, bv, gQKV, DQKV);

    attn_mma<<<dim3(SEQ / 128, NHEAD, BATCH), 256, ATTN2_SMEM>>>(
        gQKV, gab, gah, gal);

    mma_gemm<<<dim3(DMODEL / 128, MTOT / 128), 256, PIPE_SMEM>>>(
        gah, gal, gwh + 3*WSZ, gwl + 3*WSZ, bo, bo, bo, out, DMODEL);
}

// round 6
// speedup vs baseline: 2.8552x; 1.2255x over previous
#include <cuda_runtime.h>
#include <cuda_bf16.h>
#include <cstdint>

// Problem constants
#define BATCH 64
#define SEQ   512
#define DMODEL 256
#define NHEAD 4
#define HDIM  64
#define MTOT  (BATCH * SEQ)          // 32768 rows
#define DQKV  768

// ---------------- scratch (device globals; no allocation allowed) ------------
__device__ float g_QKV[MTOT * DQKV];               // fused Q|K|V, fp32
__device__ __nv_bfloat16 g_xh[MTOT * DMODEL];
__device__ __nv_bfloat16 g_xl[MTOT * DMODEL];
__device__ __nv_bfloat16 g_ah[MTOT * DMODEL];
__device__ __nv_bfloat16 g_al[MTOT * DMODEL];
__device__ __nv_bfloat16 g_wh[4 * DMODEL * DMODEL];  // wq|wk|wv|wo stacked
__device__ __nv_bfloat16 g_wl[4 * DMODEL * DMODEL];
__device__ uint32_t g_adjbits[SEQ * (SEQ / 32)];   // 512 x 16 words

// ---------------- helpers ----------------------------------------------------
__device__ __forceinline__ uint32_t f2bf2(float hi, float lo) {
    uint32_t r;
    asm("cvt.rn.bf16x2.f32 %0, %1, %2;" : "=r"(r) : "f"(hi), "f"(lo));
    return r;
}
__device__ __forceinline__ float bf_lo(uint32_t u){ return __uint_as_float(u << 16); }
__device__ __forceinline__ float bf_hi(uint32_t u){ return __uint_as_float(u & 0xffff0000u); }

__device__ __forceinline__ uint32_t s2u(const void* p){
    uint32_t a;
    asm("{ .reg .u64 t; cvta.to.shared.u64 t, %1; cvt.u32.u64 %0, t; }"
        : "=r"(a) : "l"(p));
    return a;
}
__device__ __forceinline__ void cp8(uint32_t dst, const void* src){
    asm volatile("cp.async.ca.shared.global [%0], [%1], 8;" :: "r"(dst), "l"(src));
}

#define MMA_BF16(acc, a, b) \
    asm volatile("mma.sync.aligned.m16n8k16.row.col.f32.bf16.bf16.f32 " \
        "{%0,%1,%2,%3},{%4,%5,%6,%7},{%8,%9},{%0,%1,%2,%3};" \
        : "+f"((acc)[0]), "+f"((acc)[1]), "+f"((acc)[2]), "+f"((acc)[3]) \
        : "r"((a)[0]), "r"((a)[1]), "r"((a)[2]), "r"((a)[3]), \
          "r"((b)[0]), "r"((b)[1]))

#define LDSM4(d0,d1,d2,d3,a) \
    asm volatile("ldmatrix.sync.aligned.m8n8.x4.shared.b16 {%0,%1,%2,%3},[%4];" \
        : "=r"(d0), "=r"(d1), "=r"(d2), "=r"(d3) : "r"(a))
#define LDSM4T(d0,d1,d2,d3,a) \
    asm volatile("ldmatrix.sync.aligned.m8n8.x4.trans.shared.b16 {%0,%1,%2,%3},[%4];" \
        : "=r"(d0), "=r"(d1), "=r"(d2), "=r"(d3) : "r"(a))

// ---------------- bf16 two-term split ---------------------------------------
__global__ __launch_bounds__(256)
void split_kernel(const float* __restrict__ in,
                  __nv_bfloat16* __restrict__ hi,
                  __nv_bfloat16* __restrict__ lo, int n4)
{
    int i = blockIdx.x * blockDim.x + threadIdx.x;
    if (i >= n4) return;
    float4 v = ((const float4*)in)[i];
    uint32_t h01 = f2bf2(v.y, v.x);
    uint32_t h23 = f2bf2(v.w, v.z);
    uint32_t l01 = f2bf2(v.y - bf_hi(h01), v.x - bf_lo(h01));
    uint32_t l23 = f2bf2(v.w - bf_hi(h23), v.z - bf_lo(h23));
    ((uint32_t*)hi)[2*i]     = h01;
    ((uint32_t*)hi)[2*i + 1] = h23;
    ((uint32_t*)lo)[2*i]     = l01;
    ((uint32_t*)lo)[2*i + 1] = l23;
}

__global__ __launch_bounds__(256)
void split_w(const float* __restrict__ w0, const float* __restrict__ w1,
             const float* __restrict__ w2, const float* __restrict__ w3,
             __nv_bfloat16* __restrict__ hi, __nv_bfloat16* __restrict__ lo)
{
    const int ws = blockIdx.y;
    const float* src = ws == 0 ? w0 : ws == 1 ? w1 : ws == 2 ? w2 : w3;
    const int off4 = ws * (DMODEL * DMODEL / 4);
    int i = blockIdx.x * blockDim.x + threadIdx.x;
    float4 v = ((const float4*)src)[i];
    uint32_t h01 = f2bf2(v.y, v.x);
    uint32_t h23 = f2bf2(v.w, v.z);
    uint32_t l01 = f2bf2(v.y - bf_hi(h01), v.x - bf_lo(h01));
    uint32_t l23 = f2bf2(v.w - bf_hi(h23), v.z - bf_lo(h23));
    ((uint32_t*)hi)[2*(off4+i)]     = h01;
    ((uint32_t*)hi)[2*(off4+i) + 1] = h23;
    ((uint32_t*)lo)[2*(off4+i)]     = l01;
    ((uint32_t*)lo)[2*(off4+i) + 1] = l23;
}

// ---------------- adjacency bit-pack -----------------------------------------
__global__ __launch_bounds__(256)
void pack_adj(const int* __restrict__ adj, uint32_t* __restrict__ bits)
{
    int w = blockIdx.x * blockDim.x + threadIdx.x;
    if (w >= SEQ * (SEQ / 32)) return;
    const int* p = adj + (size_t)w * 32;
    uint32_t m = 0;
#pragma unroll
    for (int i = 0; i < 32; i++) m |= (p[i] != 0 ? 1u : 0u) << i;
    bits[w] = m;
}

// ---------------- cp.async pipelined mma.sync bf16 GEMM (ldmatrix) -----------
#define SMSTRIDE 72
#define TILE_BYTES2 (128 * SMSTRIDE * 2)     // 18432
#define STAGE_B (4 * TILE_BYTES2)            // 73728
#define PIPE_SMEM (2 * STAGE_B)              // 147456

__device__ __forceinline__ void cp_tile(uint32_t smdst,
        const __nv_bfloat16* __restrict__ src, int row0, int kc, int tid)
{
#pragma unroll
    for (int it = 0; it < 4; it++) {
        int lin = it * 256 + tid;
        int r = lin >> 3, c = lin & 7;
        const char* g = (const char*)(src + (size_t)(row0 + r) * DMODEL + kc * 64) + c * 16;
        uint32_t d = smdst + r * (SMSTRIDE * 2) + c * 16;
        cp8(d, g);
        cp8(d + 8, g + 8);
    }
}

__global__ __launch_bounds__(256)
void mma_gemm(const __nv_bfloat16* __restrict__ Ah, const __nv_bfloat16* __restrict__ Al,
              const __nv_bfloat16* __restrict__ Bh, const __nv_bfloat16* __restrict__ Bl,
              const float* __restrict__ b0, const float* __restrict__ b1,
              const float* __restrict__ b2, float* __restrict__ C, int Nn)
{
    extern __shared__ char sm[];
    const uint32_t smb = s2u(sm);

    const int tid  = threadIdx.x;
    const int lane = tid & 31;
    const int warp = tid >> 5;
    const int wm   = warp >> 2;
    const int wn   = warp & 3;
    const int m0   = blockIdx.y * 128;
    const int n0   = blockIdx.x * 128;

    float acc[4][4][4];
#pragma unroll
    for (int i = 0; i < 4; i++)
#pragma unroll
        for (int j = 0; j < 4; j++)
#pragma unroll
            for (int t = 0; t < 4; t++) acc[i][j][t] = 0.f;

    const int frow = lane >> 2;
    const int fcol = (lane & 3) * 2;

    // ldmatrix per-lane address patterns (byte offsets within a tile)
    // patA (A-frag x4): rows 0-15, col halves
    const uint32_t aoff = ((wm * 64 + (lane & 15)) * SMSTRIDE + ((lane >> 4) << 3)) * 2;
    // patB (B-frag x4 non-trans, two n-tiles): rows {0-7,0-7,8-15,8-15}, col {0,8,0,8}
    const uint32_t boff = ((wn * 32 + ((lane & 7) | ((lane >> 4) << 3))) * SMSTRIDE
                           + (((lane >> 3) & 1) << 3)) * 2;

    // prologue: chunk 0 -> stage 0
    cp_tile(smb + 0 * TILE_BYTES2, Ah, m0, 0, tid);
    cp_tile(smb + 1 * TILE_BYTES2, Al, m0, 0, tid);
    cp_tile(smb + 2 * TILE_BYTES2, Bh, n0, 0, tid);
    cp_tile(smb + 3 * TILE_BYTES2, Bl, n0, 0, tid);
    asm volatile("cp.async.commit_group;");

#pragma unroll
    for (int kc = 0; kc < 4; kc++) {
        __syncthreads();
        if (kc < 3) {
            uint32_t st = smb + ((kc + 1) & 1) * STAGE_B;
            cp_tile(st + 0 * TILE_BYTES2, Ah, m0, kc + 1, tid);
            cp_tile(st + 1 * TILE_BYTES2, Al, m0, kc + 1, tid);
            cp_tile(st + 2 * TILE_BYTES2, Bh, n0, kc + 1, tid);
            cp_tile(st + 3 * TILE_BYTES2, Bl, n0, kc + 1, tid);
            asm volatile("cp.async.commit_group;");
            asm volatile("cp.async.wait_group 1;");
        } else {
            asm volatile("cp.async.wait_group 0;");
        }
        __syncthreads();

        const uint32_t stg = smb + (kc & 1) * STAGE_B;
        const uint32_t aH = stg + aoff;
        const uint32_t bH = stg + 2 * TILE_BYTES2 + boff;

#pragma unroll
        for (int ks = 0; ks < 4; ks++) {
            const uint32_t kso = ks * 32;   // ks*16 elems * 2B
            uint32_t ah[4][4], al[4][4];
#pragma unroll
            for (int mi = 0; mi < 4; mi++) {
                uint32_t ad = aH + mi * (16 * SMSTRIDE * 2) + kso;
                LDSM4(ah[mi][0], ah[mi][1], ah[mi][2], ah[mi][3], ad);
                LDSM4(al[mi][0], al[mi][1], al[mi][2], al[mi][3], ad + TILE_BYTES2);
            }
            uint32_t bh[4][2], bl[4][2];
#pragma unroll
            for (int p = 0; p < 2; p++) {
                uint32_t bd = bH + p * (16 * SMSTRIDE * 2) + kso;
                LDSM4(bh[2*p][0], bh[2*p][1], bh[2*p+1][0], bh[2*p+1][1], bd);
                LDSM4(bl[2*p][0], bl[2*p][1], bl[2*p+1][0], bl[2*p+1][1], bd + TILE_BYTES2);
            }
#pragma unroll
            for (int mi = 0; mi < 4; mi++)
#pragma unroll
                for (int ni = 0; ni < 4; ni++) {
                    MMA_BF16(acc[mi][ni], ah[mi], bh[ni]);
                    MMA_BF16(acc[mi][ni], ah[mi], bl[ni]);
                    MMA_BF16(acc[mi][ni], al[mi], bh[ni]);
                }
        }
    }

    const int reg = n0 >> 8;
    const float* bp = reg == 0 ? b0 : (reg == 1 ? b1 : b2);
    const int coff = reg << 8;
#pragma unroll
    for (int mi = 0; mi < 4; mi++) {
#pragma unroll
        for (int ni = 0; ni < 4; ni++) {
            int row = m0 + wm * 64 + mi * 16 + frow;
            int col = n0 + wn * 32 + ni * 8 + fcol;
            float bb0 = __ldg(&bp[col - coff]);
            float bb1 = __ldg(&bp[col - coff + 1]);
            float2 o0 = make_float2(acc[mi][ni][0] + bb0, acc[mi][ni][1] + bb1);
            float2 o1 = make_float2(acc[mi][ni][2] + bb0, acc[mi][ni][3] + bb1);
            *(float2*)&C[(size_t)row * Nn + col] = o0;
            *(float2*)&C[(size_t)(row + 8) * Nn + col] = o1;
        }
    }
}

// ---------------- mma.sync masked flash attention (ldmatrix) ------------------
// K and V both stored [row][d] split; V B-frags come from ldmatrix.trans.
#define QST 72
#define ATILE 18432                    // 128*72*2
#define OFF_QH 0
#define OFF_QL (1*ATILE)
#define OFF_KH (2*ATILE)
#define OFF_KL (3*ATILE)
#define OFF_VH (4*ATILE)
#define OFF_VL (5*ATILE)
#define OFF_MASK (6*ATILE)             // 110592
#define ATTN2_SMEM (OFF_MASK + 8192)   // 118784 B

__global__ __launch_bounds__(256)
void attn_mma(const float* __restrict__ QKV, const uint32_t* __restrict__ adjbits,
              __nv_bfloat16* __restrict__ Oh, __nv_bfloat16* __restrict__ Ol)
{
    extern __shared__ char sm[];
    __nv_bfloat16* sQh = (__nv_bfloat16*)(sm + OFF_QH);
    __nv_bfloat16* sQl = (__nv_bfloat16*)(sm + OFF_QL);
    __nv_bfloat16* sKh = (__nv_bfloat16*)(sm + OFF_KH);
    __nv_bfloat16* sKl = (__nv_bfloat16*)(sm + OFF_KL);
    __nv_bfloat16* sVh = (__nv_bfloat16*)(sm + OFF_VH);
    __nv_bfloat16* sVl = (__nv_bfloat16*)(sm + OFF_VL);
    uint32_t* maskS = (uint32_t*)(sm + OFF_MASK);
    const uint32_t smu = s2u(sm);

    const int tid = threadIdx.x, lane = tid & 31, warp = tid >> 5;
    const int q0 = blockIdx.x * 128;
    const int h = blockIdx.y, b = blockIdx.z;
    const size_t base = (size_t)b * SEQ * DQKV + (size_t)h * HDIM;
    const int frow = lane >> 2, fcol = (lane & 3) * 2;

    // ldmatrix per-lane patterns (byte offsets)
    const uint32_t patA = (((lane & 15)) * QST + ((lane >> 4) << 3)) * 2;
    const uint32_t patB = ((((lane & 7) | ((lane >> 4) << 3))) * QST
                           + (((lane >> 3) & 1) << 3)) * 2;

    // Q load + scale + split
#pragma unroll
    for (int it = 0; it < 8; it++) {
        int lin = it * 256 + tid;
        int row = lin >> 4, dq = lin & 15;
        float4 v = *(const float4*)&QKV[base + (size_t)(q0 + row) * DQKV + dq * 4];
        v.x *= 0.125f; v.y *= 0.125f; v.z *= 0.125f; v.w *= 0.125f;
        uint32_t h01 = f2bf2(v.y, v.x), h23 = f2bf2(v.w, v.z);
        uint32_t l01 = f2bf2(v.y - bf_hi(h01), v.x - bf_lo(h01));
        uint32_t l23 = f2bf2(v.w - bf_hi(h23), v.z - bf_lo(h23));
        int o = row * QST + dq * 4;
        *(uint32_t*)&sQh[o] = h01; *(uint32_t*)&sQh[o + 2] = h23;
        *(uint32_t*)&sQl[o] = l01; *(uint32_t*)&sQl[o + 2] = l23;
    }
#pragma unroll
    for (int it = 0; it < 8; it++) {
        int lin = it * 256 + tid;
        int row = lin >> 4, w = lin & 15;
        maskS[row * 16 + w] = adjbits[(size_t)(q0 + row) * 16 + w];
    }

    float m0r = -1e30f, m1r = -1e30f, l0r = 0.f, l1r = 0.f;
    float accO[8][4];
#pragma unroll
    for (int i = 0; i < 8; i++)
#pragma unroll
        for (int j = 0; j < 4; j++) accO[i][j] = 0.f;

    for (int t = 0; t < 4; t++) {
        const int k0 = t * 128;
        __syncthreads();
        // K and V tiles, both [row][d] split (no transpose)
#pragma unroll
        for (int it = 0; it < 8; it++) {
            int lin = it * 256 + tid;
            int row = lin >> 4, dq = lin & 15;
            float4 v = *(const float4*)&QKV[base + (size_t)(k0 + row) * DQKV + 256 + dq * 4];
            uint32_t h01 = f2bf2(v.y, v.x), h23 = f2bf2(v.w, v.z);
            uint32_t l01 = f2bf2(v.y - bf_hi(h01), v.x - bf_lo(h01));
            uint32_t l23 = f2bf2(v.w - bf_hi(h23), v.z - bf_lo(h23));
            int o = row * QST + dq * 4;
            *(uint32_t*)&sKh[o] = h01; *(uint32_t*)&sKh[o + 2] = h23;
            *(uint32_t*)&sKl[o] = l01; *(uint32_t*)&sKl[o + 2] = l23;
            float4 vv = *(const float4*)&QKV[base + (size_t)(k0 + row) * DQKV + 512 + dq * 4];
            uint32_t vh01 = f2bf2(vv.y, vv.x), vh23 = f2bf2(vv.w, vv.z);
            uint32_t vl01 = f2bf2(vv.y - bf_hi(vh01), vv.x - bf_lo(vh01));
            uint32_t vl23 = f2bf2(vv.w - bf_hi(vh23), vv.z - bf_lo(vh23));
            *(uint32_t*)&sVh[o] = vh01; *(uint32_t*)&sVh[o + 2] = vh23;
            *(uint32_t*)&sVl[o] = vl01; *(uint32_t*)&sVl[o + 2] = vl23;
        }
        __syncthreads();

        // ---- S = Q K^T (3-pass split, ldmatrix frags) ----
        float s[16][4];
#pragma unroll
        for (int i = 0; i < 16; i++)
#pragma unroll
            for (int j = 0; j < 4; j++) s[i][j] = 0.f;

#pragma unroll
        for (int ks = 0; ks < 4; ks++) {
            const uint32_t kso = ks * 32;
            uint32_t ah[4], al[4];
            {
                uint32_t qa = smu + OFF_QH + warp * (16 * QST * 2) + patA + kso;
                LDSM4(ah[0], ah[1], ah[2], ah[3], qa);
                LDSM4(al[0], al[1], al[2], al[3], qa + ATILE);
            }
#pragma unroll
            for (int p = 0; p < 8; p++) {
                uint32_t kd = smu + OFF_KH + p * (16 * QST * 2) + patB + kso;
                uint32_t bh0, bh1, bh2, bh3, bl0, bl1, bl2, bl3;
                LDSM4(bh0, bh1, bh2, bh3, kd);
                LDSM4(bl0, bl1, bl2, bl3, kd + ATILE);
                uint32_t bhp0[2] = {bh0, bh1}, bhp1[2] = {bh2, bh3};
                uint32_t blp0[2] = {bl0, bl1}, blp1[2] = {bl2, bl3};
                MMA_BF16(s[2*p],   ah, bhp0);
                MMA_BF16(s[2*p],   ah, blp0);
                MMA_BF16(s[2*p],   al, bhp0);
                MMA_BF16(s[2*p+1], ah, bhp1);
                MMA_BF16(s[2*p+1], ah, blp1);
                MMA_BF16(s[2*p+1], al, bhp1);
            }
        }

        // ---- mask + online softmax ----
        const int grow = warp * 16 + frow;
        uint4 mw0 = *(const uint4*)&maskS[grow * 16 + t * 4];
        uint4 mw1 = *(const uint4*)&maskS[(grow + 8) * 16 + t * 4];
        const uint32_t* w0p = (const uint32_t*)&mw0;
        const uint32_t* w1p = (const uint32_t*)&mw1;
        float mx0 = -1e30f, mx1 = -1e30f;
#pragma unroll
        for (int ni = 0; ni < 16; ni++) {
            int col = ni * 8 + fcol;
            uint32_t w0 = w0p[ni >> 2], w1 = w1p[ni >> 2];
            if (!((w0 >> (col & 31)) & 1u))       s[ni][0] = -1e30f;
            if (!((w0 >> ((col + 1) & 31)) & 1u)) s[ni][1] = -1e30f;
            if (!((w1 >> (col & 31)) & 1u))       s[ni][2] = -1e30f;
            if (!((w1 >> ((col + 1) & 31)) & 1u)) s[ni][3] = -1e30f;
            mx0 = fmaxf(mx0, fmaxf(s[ni][0], s[ni][1]));
            mx1 = fmaxf(mx1, fmaxf(s[ni][2], s[ni][3]));
        }
        mx0 = fmaxf(mx0, __shfl_xor_sync(0xffffffffu, mx0, 1));
        mx0 = fmaxf(mx0, __shfl_xor_sync(0xffffffffu, mx0, 2));
        mx1 = fmaxf(mx1, __shfl_xor_sync(0xffffffffu, mx1, 1));
        mx1 = fmaxf(mx1, __shfl_xor_sync(0xffffffffu, mx1, 2));
        float mn0 = fmaxf(m0r, mx0), mn1 = fmaxf(m1r, mx1);
        float sc0 = __expf(m0r - mn0), sc1 = __expf(m1r - mn1);
        float ts0 = 0.f, ts1 = 0.f;
#pragma unroll
        for (int ni = 0; ni < 16; ni++) {
            s[ni][0] = __expf(s[ni][0] - mn0);
            s[ni][1] = __expf(s[ni][1] - mn0);
            s[ni][2] = __expf(s[ni][2] - mn1);
            s[ni][3] = __expf(s[ni][3] - mn1);
            ts0 += s[ni][0] + s[ni][1];
            ts1 += s[ni][2] + s[ni][3];
        }
        ts0 += __shfl_xor_sync(0xffffffffu, ts0, 1);
        ts0 += __shfl_xor_sync(0xffffffffu, ts0, 2);
        ts1 += __shfl_xor_sync(0xffffffffu, ts1, 1);
        ts1 += __shfl_xor_sync(0xffffffffu, ts1, 2);
        l0r = l0r * sc0 + ts0;  l1r = l1r * sc1 + ts1;
        m0r = mn0;  m1r = mn1;
#pragma unroll
        for (int ni = 0; ni < 8; ni++) {
            accO[ni][0] *= sc0; accO[ni][1] *= sc0;
            accO[ni][2] *= sc1; accO[ni][3] *= sc1;
        }

        // ---- O += P V (3-pass split; P regs; V frags via ldmatrix.trans) ----
#pragma unroll
        for (int kt = 0; kt < 8; kt++) {
            uint32_t pah[4], pal[4];
            pah[0] = f2bf2(s[2*kt][1],   s[2*kt][0]);
            pal[0] = f2bf2(s[2*kt][1]   - bf_hi(pah[0]), s[2*kt][0]   - bf_lo(pah[0]));
            pah[1] = f2bf2(s[2*kt][3],   s[2*kt][2]);
            pal[1] = f2bf2(s[2*kt][3]   - bf_hi(pah[1]), s[2*kt][2]   - bf_lo(pah[1]));
            pah[2] = f2bf2(s[2*kt+1][1], s[2*kt+1][0]);
            pal[2] = f2bf2(s[2*kt+1][1] - bf_hi(pah[2]), s[2*kt+1][0] - bf_lo(pah[2]));
            pah[3] = f2bf2(s[2*kt+1][3], s[2*kt+1][2]);
            pal[3] = f2bf2(s[2*kt+1][3] - bf_hi(pah[3]), s[2*kt+1][2] - bf_lo(pah[3]));
#pragma unroll
            for (int p = 0; p < 4; p++) {
                uint32_t vd = smu + OFF_VH + kt * (16 * QST * 2) + patA + p * 32;
                uint32_t vh0, vh1, vh2, vh3, vl0, vl1, vl2, vl3;
                LDSM4T(vh0, vh1, vh2, vh3, vd);
                LDSM4T(vl0, vl1, vl2, vl3, vd + ATILE);
                uint32_t vhp0[2] = {vh0, vh1}, vhp1[2] = {vh2, vh3};
                uint32_t vlp0[2] = {vl0, vl1}, vlp1[2] = {vl2, vl3};
                MMA_BF16(accO[2*p],   pah, vhp0);
                MMA_BF16(accO[2*p],   pah, vlp0);
                MMA_BF16(accO[2*p],   pal, vhp0);
                MMA_BF16(accO[2*p+1], pah, vhp1);
                MMA_BF16(accO[2*p+1], pah, vlp1);
                MMA_BF16(accO[2*p+1], pal, vhp1);
            }
        }
    }

    float i0 = 1.f / l0r, i1 = 1.f / l1r;
    const size_t obase = (size_t)b * SEQ * DMODEL;
    const int growg = q0 + warp * 16 + frow;
#pragma unroll
    for (int ni = 0; ni < 8; ni++) {
        int col = h * HDIM + ni * 8 + fcol;
        float o00 = accO[ni][0] * i0, o01 = accO[ni][1] * i0;
        float o10 = accO[ni][2] * i1, o11 = accO[ni][3] * i1;
        uint32_t hh0 = f2bf2(o01, o00);
        uint32_t ll0 = f2bf2(o01 - bf_hi(hh0), o00 - bf_lo(hh0));
        uint32_t hh1 = f2bf2(o11, o10);
        uint32_t ll1 = f2bf2(o11 - bf_hi(hh1), o10 - bf_lo(hh1));
        *(uint32_t*)&Oh[obase + (size_t)growg * DMODEL + col] = hh0;
        *(uint32_t*)&Ol[obase + (size_t)growg * DMODEL + col] = ll0;
        *(uint32_t*)&Oh[obase + (size_t)(growg + 8) * DMODEL + col] = hh1;
        *(uint32_t*)&Ol[obase + (size_t)(growg + 8) * DMODEL + col] = ll1;
    }
}

// ---------------- launch -----------------------------------------------------
extern "C" void kernel_launch(void* const* d_in, const int* in_sizes, int n_in,
                              void* d_out, int out_size)
{
    const float* x  = (const float*)d_in[0];
    const int*   adj = (const int*) d_in[1];
    const float* wq = (const float*)d_in[2];
    const float* bq = (const float*)d_in[3];
    const float* wk = (const float*)d_in[4];
    const float* bk = (const float*)d_in[5];
    const float* wv = (const float*)d_in[6];
    const float* bv = (const float*)d_in[7];
    const float* wo = (const float*)d_in[8];
    const float* bo = (const float*)d_in[9];
    float* out = (float*)d_out;

    float* gQKV;
    __nv_bfloat16 *gxh, *gxl, *gah, *gal, *gwh, *gwl;
    uint32_t* gab;
    cudaGetSymbolAddress((void**)&gQKV, g_QKV);
    cudaGetSymbolAddress((void**)&gxh, g_xh);
    cudaGetSymbolAddress((void**)&gxl, g_xl);
    cudaGetSymbolAddress((void**)&gah, g_ah);
    cudaGetSymbolAddress((void**)&gal, g_al);
    cudaGetSymbolAddress((void**)&gwh, g_wh);
    cudaGetSymbolAddress((void**)&gwl, g_wl);
    cudaGetSymbolAddress((void**)&gab, g_adjbits);

    cudaFuncSetAttribute(mma_gemm,
                         cudaFuncAttributeMaxDynamicSharedMemorySize, PIPE_SMEM);
    cudaFuncSetAttribute(attn_mma,
                         cudaFuncAttributeMaxDynamicSharedMemorySize, ATTN2_SMEM);

    const int WSZ = DMODEL * DMODEL;           // 65536
    const int n4x = MTOT * DMODEL / 4;         // 2097152

    split_kernel<<<n4x / 256, 256>>>(x, gxh, gxl, n4x);
    split_w<<<dim3(WSZ / 4 / 256, 4), 256>>>(wq, wk, wv, wo, gwh, gwl);
    pack_adj<<<SEQ * (SEQ/32) / 256, 256>>>(adj, gab);

    mma_gemm<<<dim3(DQKV / 128, MTOT / 128), 256, PIPE_SMEM>>>(
        gxh, gxl, gwh, gwl, bq, bk, bv, gQKV, DQKV);

    attn_mma<<<dim3(SEQ / 128, NHEAD, BATCH), 256, ATTN2_SMEM>>>(
        gQKV, gab, gah, gal);

    mma_gemm<<<dim3(DMODEL / 128, MTOT / 128), 256, PIPE_SMEM>>>(
        gah, gal, gwh + 3*WSZ, gwl + 3*WSZ, bo, bo, bo, out, DMODEL);
}

// round 7
// speedup vs baseline: 3.2472x; 1.1373x over previous
#include <cuda_runtime.h>
#include <cuda_bf16.h>
#include <cstdint>

// Problem constants
#define BATCH 64
#define SEQ   512
#define DMODEL 256
#define NHEAD 4
#define HDIM  64
#define MTOT  (BATCH * SEQ)          // 32768 rows
#define DQKV  768

// ---------------- scratch (device globals; no allocation allowed) ------------
__device__ float g_Qf[MTOT * DMODEL];              // Q, fp32, pre-scaled 0.125
__device__ __nv_bfloat16 g_kh[MTOT * DMODEL];
__device__ __nv_bfloat16 g_kl[MTOT * DMODEL];
__device__ __nv_bfloat16 g_vh[MTOT * DMODEL];
__device__ __nv_bfloat16 g_vl[MTOT * DMODEL];
__device__ __nv_bfloat16 g_xh[MTOT * DMODEL];
__device__ __nv_bfloat16 g_xl[MTOT * DMODEL];
__device__ __nv_bfloat16 g_ah[MTOT * DMODEL];
__device__ __nv_bfloat16 g_al[MTOT * DMODEL];
__device__ __nv_bfloat16 g_wh[4 * DMODEL * DMODEL];  // wq|wk|wv|wo stacked
__device__ __nv_bfloat16 g_wl[4 * DMODEL * DMODEL];
__device__ uint32_t g_adjbits[SEQ * (SEQ / 32)];   // 512 x 16 words

// ---------------- helpers ----------------------------------------------------
__device__ __forceinline__ uint32_t f2bf2(float hi, float lo) {
    uint32_t r;
    asm("cvt.rn.bf16x2.f32 %0, %1, %2;" : "=r"(r) : "f"(hi), "f"(lo));
    return r;
}
__device__ __forceinline__ float bf_lo(uint32_t u){ return __uint_as_float(u << 16); }
__device__ __forceinline__ float bf_hi(uint32_t u){ return __uint_as_float(u & 0xffff0000u); }

__device__ __forceinline__ uint32_t s2u(const void* p){
    uint32_t a;
    asm("{ .reg .u64 t; cvta.to.shared.u64 t, %1; cvt.u32.u64 %0, t; }"
        : "=r"(a) : "l"(p));
    return a;
}
__device__ __forceinline__ void cp16(uint32_t dst, const void* src){
    asm volatile("cp.async.cg.shared.global [%0], [%1], 16;" :: "r"(dst), "l"(src));
}

#define MMA_BF16(acc, a, b) \
    asm volatile("mma.sync.aligned.m16n8k16.row.col.f32.bf16.bf16.f32 " \
        "{%0,%1,%2,%3},{%4,%5,%6,%7},{%8,%9},{%0,%1,%2,%3};" \
        : "+f"((acc)[0]), "+f"((acc)[1]), "+f"((acc)[2]), "+f"((acc)[3]) \
        : "r"((a)[0]), "r"((a)[1]), "r"((a)[2]), "r"((a)[3]), \
          "r"((b)[0]), "r"((b)[1]))

#define LDSM4(d0,d1,d2,d3,a) \
    asm volatile("ldmatrix.sync.aligned.m8n8.x4.shared.b16 {%0,%1,%2,%3},[%4];" \
        : "=r"(d0), "=r"(d1), "=r"(d2), "=r"(d3) : "r"(a))
#define LDSM4T(d0,d1,d2,d3,a) \
    asm volatile("ldmatrix.sync.aligned.m8n8.x4.trans.shared.b16 {%0,%1,%2,%3},[%4];" \
        : "=r"(d0), "=r"(d1), "=r"(d2), "=r"(d3) : "r"(a))

// ---------------- bf16 two-term split ---------------------------------------
__global__ __launch_bounds__(256)
void split_kernel(const float* __restrict__ in,
                  __nv_bfloat16* __restrict__ hi,
                  __nv_bfloat16* __restrict__ lo, int n4)
{
    int i = blockIdx.x * blockDim.x + threadIdx.x;
    if (i >= n4) return;
    float4 v = ((const float4*)in)[i];
    uint32_t h01 = f2bf2(v.y, v.x);
    uint32_t h23 = f2bf2(v.w, v.z);
    uint32_t l01 = f2bf2(v.y - bf_hi(h01), v.x - bf_lo(h01));
    uint32_t l23 = f2bf2(v.w - bf_hi(h23), v.z - bf_lo(h23));
    ((uint32_t*)hi)[2*i]     = h01;
    ((uint32_t*)hi)[2*i + 1] = h23;
    ((uint32_t*)lo)[2*i]     = l01;
    ((uint32_t*)lo)[2*i + 1] = l23;
}

__global__ __launch_bounds__(256)
void split_w(const float* __restrict__ w0, const float* __restrict__ w1,
             const float* __restrict__ w2, const float* __restrict__ w3,
             __nv_bfloat16* __restrict__ hi, __nv_bfloat16* __restrict__ lo)
{
    const int ws = blockIdx.y;
    const float* src = ws == 0 ? w0 : ws == 1 ? w1 : ws == 2 ? w2 : w3;
    const int off4 = ws * (DMODEL * DMODEL / 4);
    int i = blockIdx.x * blockDim.x + threadIdx.x;
    float4 v = ((const float4*)src)[i];
    uint32_t h01 = f2bf2(v.y, v.x);
    uint32_t h23 = f2bf2(v.w, v.z);
    uint32_t l01 = f2bf2(v.y - bf_hi(h01), v.x - bf_lo(h01));
    uint32_t l23 = f2bf2(v.w - bf_hi(h23), v.z - bf_lo(h23));
    ((uint32_t*)hi)[2*(off4+i)]     = h01;
    ((uint32_t*)hi)[2*(off4+i) + 1] = h23;
    ((uint32_t*)lo)[2*(off4+i)]     = l01;
    ((uint32_t*)lo)[2*(off4+i) + 1] = l23;
}

// ---------------- adjacency bit-pack -----------------------------------------
__global__ __launch_bounds__(256)
void pack_adj(const int* __restrict__ adj, uint32_t* __restrict__ bits)
{
    int w = blockIdx.x * blockDim.x + threadIdx.x;
    if (w >= SEQ * (SEQ / 32)) return;
    const int* p = adj + (size_t)w * 32;
    uint32_t m = 0;
#pragma unroll
    for (int i = 0; i < 32; i++) m |= (p[i] != 0 ? 1u : 0u) << i;
    bits[w] = m;
}

// ---------------- cp.async pipelined mma.sync bf16 GEMM (KC=32, 2 CTA/SM) ----
#define GST 40                           // padded stride (elems); r*5 mod 8 distinct
#define TILE_B32 (128 * GST * 2)         // 10240
#define STAGE32 (4 * TILE_B32)           // 40960
#define PIPE32 (2 * STAGE32)             // 81920

__device__ __forceinline__ void cp_tile32(uint32_t smdst,
        const __nv_bfloat16* __restrict__ src, int row0, int kc, int tid)
{
#pragma unroll
    for (int it = 0; it < 2; it++) {
        int lin = it * 256 + tid;
        int r = lin >> 2, c = lin & 3;
        cp16(smdst + r * (GST * 2) + c * 16,
             src + (size_t)(row0 + r) * DMODEL + kc * 32 + c * 8);
    }
}

__global__ __launch_bounds__(256, 2)
void mma_gemm(const __nv_bfloat16* __restrict__ Ah, const __nv_bfloat16* __restrict__ Al,
              const __nv_bfloat16* __restrict__ Bh, const __nv_bfloat16* __restrict__ Bl,
              const float* __restrict__ b0, const float* __restrict__ b1,
              const float* __restrict__ b2, float* __restrict__ Cf,
              __nv_bfloat16* __restrict__ Kh, __nv_bfloat16* __restrict__ Kl,
              __nv_bfloat16* __restrict__ Vh, __nv_bfloat16* __restrict__ Vl,
              int mode)
{
    extern __shared__ char sm[];
    const uint32_t smb = s2u(sm);

    const int tid  = threadIdx.x;
    const int lane = tid & 31;
    const int warp = tid >> 5;
    const int wm   = warp >> 2;
    const int wn   = warp & 3;
    const int m0   = blockIdx.y * 128;
    const int n0   = blockIdx.x * 128;

    float acc[4][4][4];
#pragma unroll
    for (int i = 0; i < 4; i++)
#pragma unroll
        for (int j = 0; j < 4; j++)
#pragma unroll
            for (int t = 0; t < 4; t++) acc[i][j][t] = 0.f;

    const int frow = lane >> 2;
    const int fcol = (lane & 3) * 2;

    const uint32_t aoff = ((wm * 64 + (lane & 15)) * GST + ((lane >> 4) << 3)) * 2;
    const uint32_t boff = ((wn * 32 + ((lane & 7) | ((lane >> 4) << 3))) * GST
                           + (((lane >> 3) & 1) << 3)) * 2;

    // prologue: chunk 0 -> stage 0
    cp_tile32(smb + 0 * TILE_B32, Ah, m0, 0, tid);
    cp_tile32(smb + 1 * TILE_B32, Al, m0, 0, tid);
    cp_tile32(smb + 2 * TILE_B32, Bh, n0, 0, tid);
    cp_tile32(smb + 3 * TILE_B32, Bl, n0, 0, tid);
    asm volatile("cp.async.commit_group;");

#pragma unroll
    for (int kc = 0; kc < 8; kc++) {
        __syncthreads();
        if (kc < 7) {
            uint32_t st = smb + ((kc + 1) & 1) * STAGE32;
            cp_tile32(st + 0 * TILE_B32, Ah, m0, kc + 1, tid);
            cp_tile32(st + 1 * TILE_B32, Al, m0, kc + 1, tid);
            cp_tile32(st + 2 * TILE_B32, Bh, n0, kc + 1, tid);
            cp_tile32(st + 3 * TILE_B32, Bl, n0, kc + 1, tid);
            asm volatile("cp.async.commit_group;");
            asm volatile("cp.async.wait_group 1;");
        } else {
            asm volatile("cp.async.wait_group 0;");
        }
        __syncthreads();

        const uint32_t stg = smb + (kc & 1) * STAGE32;
        const uint32_t aH = stg + aoff;
        const uint32_t bH = stg + 2 * TILE_B32 + boff;

#pragma unroll
        for (int ks = 0; ks < 2; ks++) {
            const uint32_t kso = ks * 32;
            uint32_t ah[4][4], al[4][4];
#pragma unroll
            for (int mi = 0; mi < 4; mi++) {
                uint32_t ad = aH + mi * (16 * GST * 2) + kso;
                LDSM4(ah[mi][0], ah[mi][1], ah[mi][2], ah[mi][3], ad);
                LDSM4(al[mi][0], al[mi][1], al[mi][2], al[mi][3], ad + TILE_B32);
            }
            uint32_t bh[4][2], bl[4][2];
#pragma unroll
            for (int p = 0; p < 2; p++) {
                uint32_t bd = bH + p * (16 * GST * 2) + kso;
                LDSM4(bh[2*p][0], bh[2*p][1], bh[2*p+1][0], bh[2*p+1][1], bd);
                LDSM4(bl[2*p][0], bl[2*p][1], bl[2*p+1][0], bl[2*p+1][1], bd + TILE_B32);
            }
            // pass-major: 16 independent chains per pass
#pragma unroll
            for (int mi = 0; mi < 4; mi++)
#pragma unroll
                for (int ni = 0; ni < 4; ni++) MMA_BF16(acc[mi][ni], ah[mi], bh[ni]);
#pragma unroll
            for (int mi = 0; mi < 4; mi++)
#pragma unroll
                for (int ni = 0; ni < 4; ni++) MMA_BF16(acc[mi][ni], ah[mi], bl[ni]);
#pragma unroll
            for (int mi = 0; mi < 4; mi++)
#pragma unroll
                for (int ni = 0; ni < 4; ni++) MMA_BF16(acc[mi][ni], al[mi], bh[ni]);
        }
    }

    const int reg = n0 >> 8;
    const float* bp = reg == 0 ? b0 : (reg == 1 ? b1 : b2);
    const int coff = reg << 8;
#pragma unroll
    for (int mi = 0; mi < 4; mi++) {
#pragma unroll
        for (int ni = 0; ni < 4; ni++) {
            int row = m0 + wm * 64 + mi * 16 + frow;
            int col = n0 + wn * 32 + ni * 8 + fcol;
            int cc = col - coff;
            float bb0 = __ldg(&bp[cc]);
            float bb1 = __ldg(&bp[cc + 1]);
            float v0 = acc[mi][ni][0] + bb0, v1 = acc[mi][ni][1] + bb1;
            float v2 = acc[mi][ni][2] + bb0, v3 = acc[mi][ni][3] + bb1;
            if (mode == 0) {
                *(float2*)&Cf[(size_t)row * DMODEL + col] = make_float2(v0, v1);
                *(float2*)&Cf[(size_t)(row + 8) * DMODEL + col] = make_float2(v2, v3);
            } else if (reg == 0) {
                // Q: pre-scale by 1/sqrt(HD)
                *(float2*)&Cf[(size_t)row * DMODEL + cc] =
                    make_float2(v0 * 0.125f, v1 * 0.125f);
                *(float2*)&Cf[(size_t)(row + 8) * DMODEL + cc] =
                    make_float2(v2 * 0.125f, v3 * 0.125f);
            } else {
                __nv_bfloat16* Ph = (reg == 1) ? Kh : Vh;
                __nv_bfloat16* Pl = (reg == 1) ? Kl : Vl;
                uint32_t hh0 = f2bf2(v1, v0);
                uint32_t ll0 = f2bf2(v1 - bf_hi(hh0), v0 - bf_lo(hh0));
                uint32_t hh1 = f2bf2(v3, v2);
                uint32_t ll1 = f2bf2(v3 - bf_hi(hh1), v2 - bf_lo(hh1));
                *(uint32_t*)&Ph[(size_t)row * DMODEL + cc] = hh0;
                *(uint32_t*)&Pl[(size_t)row * DMODEL + cc] = ll0;
                *(uint32_t*)&Ph[(size_t)(row + 8) * DMODEL + cc] = hh1;
                *(uint32_t*)&Pl[(size_t)(row + 8) * DMODEL + cc] = ll1;
            }
        }
    }
}

// ---------------- mma.sync masked flash attention (cp.async KV, 2 CTA/SM) ----
#define QST 72
#define QTILE 18432                    // 128*72*2
#define TKV 9216                       // 64*72*2
#define STAGE_KV (4 * TKV)             // 36864: Kh|Kl|Vh|Vl
#define OFF_KV (2 * QTILE)             // 36864
#define ATTN3_SMEM (OFF_KV + 2 * STAGE_KV)   // 110592

__global__ __launch_bounds__(256, 2)
void attn_mma(const float* __restrict__ Qf,
              const __nv_bfloat16* __restrict__ Kh, const __nv_bfloat16* __restrict__ Kl,
              const __nv_bfloat16* __restrict__ Vh, const __nv_bfloat16* __restrict__ Vl,
              const uint32_t* __restrict__ adjbits,
              __nv_bfloat16* __restrict__ Oh, __nv_bfloat16* __restrict__ Ol)
{
    extern __shared__ char sm[];
    __nv_bfloat16* sQh = (__nv_bfloat16*)(sm);
    __nv_bfloat16* sQl = (__nv_bfloat16*)(sm + QTILE);
    const uint32_t smu = s2u(sm);

    const int tid = threadIdx.x, lane = tid & 31, warp = tid >> 5;
    const int q0 = blockIdx.x * 128;
    const int h = blockIdx.y, b = blockIdx.z;
    const size_t rbase = (size_t)b * SEQ;   // row base in [MTOT]
    const int hc = h * HDIM;
    const int frow = lane >> 2, fcol = (lane & 3) * 2;

    const uint32_t patA = (((lane & 15)) * QST + ((lane >> 4) << 3)) * 2;
    const uint32_t patB = ((((lane & 7) | ((lane >> 4) << 3))) * QST
                           + (((lane >> 3) & 1) << 3)) * 2;

    // Q load (pre-scaled fp32) + split
#pragma unroll
    for (int it = 0; it < 8; it++) {
        int lin = it * 256 + tid;
        int row = lin >> 4, dq = lin & 15;
        float4 v = *(const float4*)&Qf[(rbase + q0 + row) * DMODEL + hc + dq * 4];
        uint32_t h01 = f2bf2(v.y, v.x), h23 = f2bf2(v.w, v.z);
        uint32_t l01 = f2bf2(v.y - bf_hi(h01), v.x - bf_lo(h01));
        uint32_t l23 = f2bf2(v.w - bf_hi(h23), v.z - bf_lo(h23));
        int o = row * QST + dq * 4;
        *(uint32_t*)&sQh[o] = h01; *(uint32_t*)&sQh[o + 2] = h23;
        *(uint32_t*)&sQl[o] = l01; *(uint32_t*)&sQl[o + 2] = l23;
    }

    // KV stage fill helper (inline): 64 keys x 64 d, 4 tiles
    auto cp_kv = [&](int st, int t){
        uint32_t sb = smu + OFF_KV + st * STAGE_KV;
#pragma unroll
        for (int it = 0; it < 2; it++) {
            int lin = it * 256 + tid;
            int r = lin >> 3, c = lin & 7;
            size_t g = (rbase + t * 64 + r) * DMODEL + hc + c * 8;
            uint32_t d = r * (QST * 2) + c * 16;
            cp16(sb + 0 * TKV + d, Kh + g);
            cp16(sb + 1 * TKV + d, Kl + g);
            cp16(sb + 2 * TKV + d, Vh + g);
            cp16(sb + 3 * TKV + d, Vl + g);
        }
    };

    float m0r = -1e30f, m1r = -1e30f, l0r = 0.f, l1r = 0.f;
    float accO[8][4];
#pragma unroll
    for (int i = 0; i < 8; i++)
#pragma unroll
        for (int j = 0; j < 4; j++) accO[i][j] = 0.f;

    cp_kv(0, 0);
    asm volatile("cp.async.commit_group;");

    for (int t = 0; t < 8; t++) {
        __syncthreads();   // stage (t+1)&1 free (read in iter t-2); Q ready at t=0
        if (t < 7) {
            cp_kv((t + 1) & 1, t + 1);
            asm volatile("cp.async.commit_group;");
            asm volatile("cp.async.wait_group 1;");
        } else {
            asm volatile("cp.async.wait_group 0;");
        }
        __syncthreads();

        const uint32_t kvb = smu + OFF_KV + (t & 1) * STAGE_KV;

        // ---- S = Q K^T (3-pass split, pass-major) ----
        float s[8][4];
#pragma unroll
        for (int i = 0; i < 8; i++)
#pragma unroll
            for (int j = 0; j < 4; j++) s[i][j] = 0.f;

#pragma unroll
        for (int ks = 0; ks < 4; ks++) {
            const uint32_t kso = ks * 32;
            uint32_t ah[4], al[4];
            {
                uint32_t qa = smu + warp * (16 * QST * 2) + patA + kso;
                LDSM4(ah[0], ah[1], ah[2], ah[3], qa);
                LDSM4(al[0], al[1], al[2], al[3], qa + QTILE);
            }
            uint32_t bh[8][2], bl[8][2];
#pragma unroll
            for (int p = 0; p < 4; p++) {
                uint32_t kd = kvb + p * (16 * QST * 2) + patB + kso;
                LDSM4(bh[2*p][0], bh[2*p][1], bh[2*p+1][0], bh[2*p+1][1], kd);
                LDSM4(bl[2*p][0], bl[2*p][1], bl[2*p+1][0], bl[2*p+1][1], kd + TKV);
            }
#pragma unroll
            for (int ni = 0; ni < 8; ni++) MMA_BF16(s[ni], ah, bh[ni]);
#pragma unroll
            for (int ni = 0; ni < 8; ni++) MMA_BF16(s[ni], ah, bl[ni]);
#pragma unroll
            for (int ni = 0; ni < 8; ni++) MMA_BF16(s[ni], al, bh[ni]);
        }

        // ---- mask (from L2) + online softmax ----
        const int grow = warp * 16 + frow;
        uint2 a0 = *(const uint2*)&adjbits[(size_t)(q0 + grow) * 16 + t * 2];
        uint2 a1 = *(const uint2*)&adjbits[(size_t)(q0 + grow + 8) * 16 + t * 2];
        uint32_t w0p[2] = {a0.x, a0.y};
        uint32_t w1p[2] = {a1.x, a1.y};
        float mx0 = -1e30f, mx1 = -1e30f;
#pragma unroll
        for (int ni = 0; ni < 8; ni++) {
            int col = ni * 8 + fcol;
            uint32_t w0 = w0p[ni >> 2], w1 = w1p[ni >> 2];
            if (!((w0 >> (col & 31)) & 1u))       s[ni][0] = -1e30f;
            if (!((w0 >> ((col + 1) & 31)) & 1u)) s[ni][1] = -1e30f;
            if (!((w1 >> (col & 31)) & 1u))       s[ni][2] = -1e30f;
            if (!((w1 >> ((col + 1) & 31)) & 1u)) s[ni][3] = -1e30f;
            mx0 = fmaxf(mx0, fmaxf(s[ni][0], s[ni][1]));
            mx1 = fmaxf(mx1, fmaxf(s[ni][2], s[ni][3]));
        }
        mx0 = fmaxf(mx0, __shfl_xor_sync(0xffffffffu, mx0, 1));
        mx0 = fmaxf(mx0, __shfl_xor_sync(0xffffffffu, mx0, 2));
        mx1 = fmaxf(mx1, __shfl_xor_sync(0xffffffffu, mx1, 1));
        mx1 = fmaxf(mx1, __shfl_xor_sync(0xffffffffu, mx1, 2));
        float mn0 = fmaxf(m0r, mx0), mn1 = fmaxf(m1r, mx1);
        float sc0 = __expf(m0r - mn0), sc1 = __expf(m1r - mn1);
        float ts0 = 0.f, ts1 = 0.f;
#pragma unroll
        for (int ni = 0; ni < 8; ni++) {
            s[ni][0] = __expf(s[ni][0] - mn0);
            s[ni][1] = __expf(s[ni][1] - mn0);
            s[ni][2] = __expf(s[ni][2] - mn1);
            s[ni][3] = __expf(s[ni][3] - mn1);
            ts0 += s[ni][0] + s[ni][1];
            ts1 += s[ni][2] + s[ni][3];
        }
        ts0 += __shfl_xor_sync(0xffffffffu, ts0, 1);
        ts0 += __shfl_xor_sync(0xffffffffu, ts0, 2);
        ts1 += __shfl_xor_sync(0xffffffffu, ts1, 1);
        ts1 += __shfl_xor_sync(0xffffffffu, ts1, 2);
        l0r = l0r * sc0 + ts0;  l1r = l1r * sc1 + ts1;
        m0r = mn0;  m1r = mn1;
#pragma unroll
        for (int ni = 0; ni < 8; ni++) {
            accO[ni][0] *= sc0; accO[ni][1] *= sc0;
            accO[ni][2] *= sc1; accO[ni][3] *= sc1;
        }

        // ---- O += P V (3-pass split, pass-major; V via ldmatrix.trans) ----
#pragma unroll
        for (int kt = 0; kt < 4; kt++) {
            uint32_t pah[4], pal[4];
            pah[0] = f2bf2(s[2*kt][1],   s[2*kt][0]);
            pal[0] = f2bf2(s[2*kt][1]   - bf_hi(pah[0]), s[2*kt][0]   - bf_lo(pah[0]));
            pah[1] = f2bf2(s[2*kt][3],   s[2*kt][2]);
            pal[1] = f2bf2(s[2*kt][3]   - bf_hi(pah[1]), s[2*kt][2]   - bf_lo(pah[1]));
            pah[2] = f2bf2(s[2*kt+1][1], s[2*kt+1][0]);
            pal[2] = f2bf2(s[2*kt+1][1] - bf_hi(pah[2]), s[2*kt+1][0] - bf_lo(pah[2]));
            pah[3] = f2bf2(s[2*kt+1][3], s[2*kt+1][2]);
            pal[3] = f2bf2(s[2*kt+1][3] - bf_hi(pah[3]), s[2*kt+1][2] - bf_lo(pah[3]));
            uint32_t vh[8][2], vl[8][2];
#pragma unroll
            for (int p = 0; p < 4; p++) {
                uint32_t vd = kvb + 2 * TKV + kt * (16 * QST * 2) + patA + p * 32;
                LDSM4T(vh[2*p][0], vh[2*p][1], vh[2*p+1][0], vh[2*p+1][1], vd);
                LDSM4T(vl[2*p][0], vl[2*p][1], vl[2*p+1][0], vl[2*p+1][1], vd + TKV);
            }
#pragma unroll
            for (int d = 0; d < 8; d++) MMA_BF16(accO[d], pah, vh[d]);
#pragma unroll
            for (int d = 0; d < 8; d++) MMA_BF16(accO[d], pah, vl[d]);
#pragma unroll
            for (int d = 0; d < 8; d++) MMA_BF16(accO[d], pal, vh[d]);
        }
    }

    float i0 = 1.f / l0r, i1 = 1.f / l1r;
    const size_t obase = rbase * DMODEL;
    const int growg = q0 + warp * 16 + frow;
#pragma unroll
    for (int ni = 0; ni < 8; ni++) {
        int col = hc + ni * 8 + fcol;
        float o00 = accO[ni][0] * i0, o01 = accO[ni][1] * i0;
        float o10 = accO[ni][2] * i1, o11 = accO[ni][3] * i1;
        uint32_t hh0 = f2bf2(o01, o00);
        uint32_t ll0 = f2bf2(o01 - bf_hi(hh0), o00 - bf_lo(hh0));
        uint32_t hh1 = f2bf2(o11, o10);
        uint32_t ll1 = f2bf2(o11 - bf_hi(hh1), o10 - bf_lo(hh1));
        *(uint32_t*)&Oh[obase + (size_t)growg * DMODEL + col] = hh0;
        *(uint32_t*)&Ol[obase + (size_t)growg * DMODEL + col] = ll0;
        *(uint32_t*)&Oh[obase + (size_t)(growg + 8) * DMODEL + col] = hh1;
        *(uint32_t*)&Ol[obase + (size_t)(growg + 8) * DMODEL + col] = ll1;
    }
}

// ---------------- launch -----------------------------------------------------
extern "C" void kernel_launch(void* const* d_in, const int* in_sizes, int n_in,
                              void* d_out, int out_size)
{
    const float* x  = (const float*)d_in[0];
    const int*   adj = (const int*) d_in[1];
    const float* wq = (const float*)d_in[2];
    const float* bq = (const float*)d_in[3];
    const float* wk = (const float*)d_in[4];
    const float* bk = (const float*)d_in[5];
    const float* wv = (const float*)d_in[6];
    const float* bv = (const float*)d_in[7];
    const float* wo = (const float*)d_in[8];
    const float* bo = (const float*)d_in[9];
    float* out = (float*)d_out;

    float* gQf;
    __nv_bfloat16 *gkh, *gkl, *gvh, *gvl;
    __nv_bfloat16 *gxh, *gxl, *gah, *gal, *gwh, *gwl;
    uint32_t* gab;
    cudaGetSymbolAddress((void**)&gQf, g_Qf);
    cudaGetSymbolAddress((void**)&gkh, g_kh);
    cudaGetSymbolAddress((void**)&gkl, g_kl);
    cudaGetSymbolAddress((void**)&gvh, g_vh);
    cudaGetSymbolAddress((void**)&gvl, g_vl);
    cudaGetSymbolAddress((void**)&gxh, g_xh);
    cudaGetSymbolAddress((void**)&gxl, g_xl);
    cudaGetSymbolAddress((void**)&gah, g_ah);
    cudaGetSymbolAddress((void**)&gal, g_al);
    cudaGetSymbolAddress((void**)&gwh, g_wh);
    cudaGetSymbolAddress((void**)&gwl, g_wl);
    cudaGetSymbolAddress((void**)&gab, g_adjbits);

    cudaFuncSetAttribute(mma_gemm,
                         cudaFuncAttributeMaxDynamicSharedMemorySize, PIPE32);
    cudaFuncSetAttribute(attn_mma,
                         cudaFuncAttributeMaxDynamicSharedMemorySize, ATTN3_SMEM);

    const int WSZ = DMODEL * DMODEL;           // 65536
    const int n4x = MTOT * DMODEL / 4;         // 2097152

    split_kernel<<<n4x / 256, 256>>>(x, gxh, gxl, n4x);
    split_w<<<dim3(WSZ / 4 / 256, 4), 256>>>(wq, wk, wv, wo, gwh, gwl);
    pack_adj<<<SEQ * (SEQ/32) / 256, 256>>>(adj, gab);

    // fused QKV projection: Q (fp32, pre-scaled) + K,V (bf16 split)
    mma_gemm<<<dim3(DQKV / 128, MTOT / 128), 256, PIPE32>>>(
        gxh, gxl, gwh, gwl, bq, bk, bv, gQf, gkh, gkl, gvh, gvl, 1);

    attn_mma<<<dim3(SEQ / 128, NHEAD, BATCH), 256, ATTN3_SMEM>>>(
        gQf, gkh, gkl, gvh, gvl, gab, gah, gal);

    mma_gemm<<<dim3(DMODEL / 128, MTOT / 128), 256, PIPE32>>>(
        gah, gal, gwh + 3*WSZ, gwl + 3*WSZ, bo, bo, bo, out,
        gkh, gkl, gvh, gvl, 0);
}

// round 8
// speedup vs baseline: 4.3757x; 1.3475x over previous
#include <cuda_runtime.h>
#include <cuda_fp16.h>
#include <cstdint>

// Problem constants
#define BATCH 64
#define SEQ   512
#define DMODEL 256
#define NHEAD 4
#define HDIM  64
#define MTOT  (BATCH * SEQ)          // 32768 rows
#define DQKV  768

// ---------------- scratch (device globals; no allocation allowed) ------------
__device__ float  g_Qf[MTOT * DMODEL];             // Q, fp32, pre-scaled 0.125
__device__ __half g_kh[MTOT * DMODEL];             // K, single fp16
__device__ __half g_vh[MTOT * DMODEL];             // V, single fp16
__device__ __half g_xh[MTOT * DMODEL];             // x hi
__device__ __half g_xl[MTOT * DMODEL];             // x lo
__device__ __half g_ah[MTOT * DMODEL];             // attn out hi
__device__ __half g_al[MTOT * DMODEL];             // attn out lo
__device__ __half g_wh[4 * DMODEL * DMODEL];       // wq|wk|wv|wo, single fp16
__device__ uint32_t g_adjbits[SEQ * (SEQ / 32)];   // 512 x 16 words

// ---------------- helpers ----------------------------------------------------
__device__ __forceinline__ uint32_t f2h2(float hi, float lo) {
    uint32_t r;
    asm("cvt.rn.f16x2.f32 %0, %1, %2;" : "=r"(r) : "f"(hi), "f"(lo));
    return r;
}
__device__ __forceinline__ float h_lo(uint32_t u){
    return __half2float(__ushort_as_half((unsigned short)(u & 0xffffu)));
}
__device__ __forceinline__ float h_hi(uint32_t u){
    return __half2float(__ushort_as_half((unsigned short)(u >> 16)));
}

__device__ __forceinline__ uint32_t s2u(const void* p){
    uint32_t a;
    asm("{ .reg .u64 t; cvta.to.shared.u64 t, %1; cvt.u32.u64 %0, t; }"
        : "=r"(a) : "l"(p));
    return a;
}
__device__ __forceinline__ void cp16(uint32_t dst, const void* src){
    asm volatile("cp.async.cg.shared.global [%0], [%1], 16;" :: "r"(dst), "l"(src));
}

#define MMA_F16(acc, a, b) \
    asm volatile("mma.sync.aligned.m16n8k16.row.col.f32.f16.f16.f32 " \
        "{%0,%1,%2,%3},{%4,%5,%6,%7},{%8,%9},{%0,%1,%2,%3};" \
        : "+f"((acc)[0]), "+f"((acc)[1]), "+f"((acc)[2]), "+f"((acc)[3]) \
        : "r"((a)[0]), "r"((a)[1]), "r"((a)[2]), "r"((a)[3]), \
          "r"((b)[0]), "r"((b)[1]))

#define LDSM4(d0,d1,d2,d3,a) \
    asm volatile("ldmatrix.sync.aligned.m8n8.x4.shared.b16 {%0,%1,%2,%3},[%4];" \
        : "=r"(d0), "=r"(d1), "=r"(d2), "=r"(d3) : "r"(a))
#define LDSM4T(d0,d1,d2,d3,a) \
    asm volatile("ldmatrix.sync.aligned.m8n8.x4.trans.shared.b16 {%0,%1,%2,%3},[%4];" \
        : "=r"(d0), "=r"(d1), "=r"(d2), "=r"(d3) : "r"(a))

// ---------------- fp16 two-term split of x -----------------------------------
__global__ __launch_bounds__(256)
void split_kernel(const float* __restrict__ in,
                  __half* __restrict__ hi, __half* __restrict__ lo, int n4)
{
    int i = blockIdx.x * blockDim.x + threadIdx.x;
    if (i >= n4) return;
    float4 v = ((const float4*)in)[i];
    uint32_t h01 = f2h2(v.y, v.x);
    uint32_t h23 = f2h2(v.w, v.z);
    uint32_t l01 = f2h2(v.y - h_hi(h01), v.x - h_lo(h01));
    uint32_t l23 = f2h2(v.w - h_hi(h23), v.z - h_lo(h23));
    ((uint32_t*)hi)[2*i]     = h01;
    ((uint32_t*)hi)[2*i + 1] = h23;
    ((uint32_t*)lo)[2*i]     = l01;
    ((uint32_t*)lo)[2*i + 1] = l23;
}

// weights: single fp16 rounding, 4 matrices in one launch
__global__ __launch_bounds__(256)
void split_w(const float* __restrict__ w0, const float* __restrict__ w1,
             const float* __restrict__ w2, const float* __restrict__ w3,
             __half* __restrict__ hi)
{
    const int ws = blockIdx.y;
    const float* src = ws == 0 ? w0 : ws == 1 ? w1 : ws == 2 ? w2 : w3;
    const int off4 = ws * (DMODEL * DMODEL / 4);
    int i = blockIdx.x * blockDim.x + threadIdx.x;
    float4 v = ((const float4*)src)[i];
    ((uint32_t*)hi)[2*(off4+i)]     = f2h2(v.y, v.x);
    ((uint32_t*)hi)[2*(off4+i) + 1] = f2h2(v.w, v.z);
}

// ---------------- adjacency bit-pack -----------------------------------------
__global__ __launch_bounds__(256)
void pack_adj(const int* __restrict__ adj, uint32_t* __restrict__ bits)
{
    int w = blockIdx.x * blockDim.x + threadIdx.x;
    if (w >= SEQ * (SEQ / 32)) return;
    const int* p = adj + (size_t)w * 32;
    uint32_t m = 0;
#pragma unroll
    for (int i = 0; i < 32; i++) m |= (p[i] != 0 ? 1u : 0u) << i;
    bits[w] = m;
}

// ---------------- cp.async pipelined fp16 2-pass GEMM (KC=32, 2 CTA/SM) ------
#define GST 40                           // padded stride (elems)
#define TILE_B32 (128 * GST * 2)         // 10240
#define STAGE32 (3 * TILE_B32)           // 30720: Ah|Al|Bh
#define PIPE32 (2 * STAGE32)             // 61440

__device__ __forceinline__ void cp_tile32(uint32_t smdst,
        const __half* __restrict__ src, int row0, int kc, int tid)
{
#pragma unroll
    for (int it = 0; it < 2; it++) {
        int lin = it * 256 + tid;
        int r = lin >> 2, c = lin & 3;
        cp16(smdst + r * (GST * 2) + c * 16,
             src + (size_t)(row0 + r) * DMODEL + kc * 32 + c * 8);
    }
}

__global__ __launch_bounds__(256, 2)
void mma_gemm(const __half* __restrict__ Ah, const __half* __restrict__ Al,
              const __half* __restrict__ Bh,
              const float* __restrict__ b0, const float* __restrict__ b1,
              const float* __restrict__ b2, float* __restrict__ Cf,
              __half* __restrict__ Kh, __half* __restrict__ Vh, int mode)
{
    extern __shared__ char sm[];
    const uint32_t smb = s2u(sm);

    const int tid  = threadIdx.x;
    const int lane = tid & 31;
    const int warp = tid >> 5;
    const int wm   = warp >> 2;
    const int wn   = warp & 3;
    const int m0   = blockIdx.y * 128;
    const int n0   = blockIdx.x * 128;

    float acc[4][4][4];
#pragma unroll
    for (int i = 0; i < 4; i++)
#pragma unroll
        for (int j = 0; j < 4; j++)
#pragma unroll
            for (int t = 0; t < 4; t++) acc[i][j][t] = 0.f;

    const int frow = lane >> 2;
    const int fcol = (lane & 3) * 2;

    const uint32_t aoff = ((wm * 64 + (lane & 15)) * GST + ((lane >> 4) << 3)) * 2;
    const uint32_t boff = ((wn * 32 + ((lane & 7) | ((lane >> 4) << 3))) * GST
                           + (((lane >> 3) & 1) << 3)) * 2;

    cp_tile32(smb + 0 * TILE_B32, Ah, m0, 0, tid);
    cp_tile32(smb + 1 * TILE_B32, Al, m0, 0, tid);
    cp_tile32(smb + 2 * TILE_B32, Bh, n0, 0, tid);
    asm volatile("cp.async.commit_group;");

#pragma unroll
    for (int kc = 0; kc < 8; kc++) {
        __syncthreads();
        if (kc < 7) {
            uint32_t st = smb + ((kc + 1) & 1) * STAGE32;
            cp_tile32(st + 0 * TILE_B32, Ah, m0, kc + 1, tid);
            cp_tile32(st + 1 * TILE_B32, Al, m0, kc + 1, tid);
            cp_tile32(st + 2 * TILE_B32, Bh, n0, kc + 1, tid);
            asm volatile("cp.async.commit_group;");
            asm volatile("cp.async.wait_group 1;");
        } else {
            asm volatile("cp.async.wait_group 0;");
        }
        __syncthreads();

        const uint32_t stg = smb + (kc & 1) * STAGE32;
        const uint32_t aH = stg + aoff;
        const uint32_t bH = stg + 2 * TILE_B32 + boff;

#pragma unroll
        for (int ks = 0; ks < 2; ks++) {
            const uint32_t kso = ks * 32;
            uint32_t ah[4][4], al[4][4], bh[4][2];
#pragma unroll
            for (int mi = 0; mi < 4; mi++) {
                uint32_t ad = aH + mi * (16 * GST * 2) + kso;
                LDSM4(ah[mi][0], ah[mi][1], ah[mi][2], ah[mi][3], ad);
                LDSM4(al[mi][0], al[mi][1], al[mi][2], al[mi][3], ad + TILE_B32);
            }
#pragma unroll
            for (int p = 0; p < 2; p++) {
                uint32_t bd = bH + p * (16 * GST * 2) + kso;
                LDSM4(bh[2*p][0], bh[2*p][1], bh[2*p+1][0], bh[2*p+1][1], bd);
            }
            // pass-major: 16 independent chains per pass
#pragma unroll
            for (int mi = 0; mi < 4; mi++)
#pragma unroll
                for (int ni = 0; ni < 4; ni++) MMA_F16(acc[mi][ni], ah[mi], bh[ni]);
#pragma unroll
            for (int mi = 0; mi < 4; mi++)
#pragma unroll
                for (int ni = 0; ni < 4; ni++) MMA_F16(acc[mi][ni], al[mi], bh[ni]);
        }
    }

    const int reg = n0 >> 8;
    const float* bp = reg == 0 ? b0 : (reg == 1 ? b1 : b2);
    const int coff = reg << 8;
#pragma unroll
    for (int mi = 0; mi < 4; mi++) {
#pragma unroll
        for (int ni = 0; ni < 4; ni++) {
            int row = m0 + wm * 64 + mi * 16 + frow;
            int col = n0 + wn * 32 + ni * 8 + fcol;
            int cc = col - coff;
            float bb0 = __ldg(&bp[cc]);
            float bb1 = __ldg(&bp[cc + 1]);
            float v0 = acc[mi][ni][0] + bb0, v1 = acc[mi][ni][1] + bb1;
            float v2 = acc[mi][ni][2] + bb0, v3 = acc[mi][ni][3] + bb1;
            if (mode == 0) {
                *(float2*)&Cf[(size_t)row * DMODEL + col] = make_float2(v0, v1);
                *(float2*)&Cf[(size_t)(row + 8) * DMODEL + col] = make_float2(v2, v3);
            } else if (reg == 0) {
                *(float2*)&Cf[(size_t)row * DMODEL + cc] =
                    make_float2(v0 * 0.125f, v1 * 0.125f);
                *(float2*)&Cf[(size_t)(row + 8) * DMODEL + cc] =
                    make_float2(v2 * 0.125f, v3 * 0.125f);
            } else {
                __half* Ph = (reg == 1) ? Kh : Vh;
                *(uint32_t*)&Ph[(size_t)row * DMODEL + cc] = f2h2(v1, v0);
                *(uint32_t*)&Ph[(size_t)(row + 8) * DMODEL + cc] = f2h2(v3, v2);
            }
        }
    }
}

// ---------------- fp16 2-pass masked flash attention (cp.async KV) -----------
#define QST 72
#define QTILE 18432                    // 128*72*2
#define TKV 9216                       // 64*72*2
#define STAGE_KV (2 * TKV)             // 18432: Kh|Vh
#define OFF_KV (2 * QTILE)             // 36864
#define ATTN4_SMEM (OFF_KV + 2 * STAGE_KV)   // 73728

__global__ __launch_bounds__(256, 2)
void attn_mma(const float* __restrict__ Qf,
              const __half* __restrict__ Kh, const __half* __restrict__ Vh,
              const uint32_t* __restrict__ adjbits,
              __half* __restrict__ Oh, __half* __restrict__ Ol)
{
    extern __shared__ char sm[];
    __half* sQh = (__half*)(sm);
    __half* sQl = (__half*)(sm + QTILE);
    const uint32_t smu = s2u(sm);

    const int tid = threadIdx.x, lane = tid & 31, warp = tid >> 5;
    const int q0 = blockIdx.x * 128;
    const int h = blockIdx.y, b = blockIdx.z;
    const size_t rbase = (size_t)b * SEQ;
    const int hc = h * HDIM;
    const int frow = lane >> 2, fcol = (lane & 3) * 2;

    const uint32_t patA = (((lane & 15)) * QST + ((lane >> 4) << 3)) * 2;
    const uint32_t patB = ((((lane & 7) | ((lane >> 4) << 3))) * QST
                           + (((lane >> 3) & 1) << 3)) * 2;

    // Q load (pre-scaled fp32) + fp16 split
#pragma unroll
    for (int it = 0; it < 8; it++) {
        int lin = it * 256 + tid;
        int row = lin >> 4, dq = lin & 15;
        float4 v = *(const float4*)&Qf[(rbase + q0 + row) * DMODEL + hc + dq * 4];
        uint32_t h01 = f2h2(v.y, v.x), h23 = f2h2(v.w, v.z);
        uint32_t l01 = f2h2(v.y - h_hi(h01), v.x - h_lo(h01));
        uint32_t l23 = f2h2(v.w - h_hi(h23), v.z - h_lo(h23));
        int o = row * QST + dq * 4;
        *(uint32_t*)&sQh[o] = h01; *(uint32_t*)&sQh[o + 2] = h23;
        *(uint32_t*)&sQl[o] = l01; *(uint32_t*)&sQl[o + 2] = l23;
    }

    auto cp_kv = [&](int st, int t){
        uint32_t sb = smu + OFF_KV + st * STAGE_KV;
#pragma unroll
        for (int it = 0; it < 2; it++) {
            int lin = it * 256 + tid;
            int r = lin >> 3, c = lin & 7;
            size_t g = (rbase + t * 64 + r) * DMODEL + hc + c * 8;
            uint32_t d = r * (QST * 2) + c * 16;
            cp16(sb + d, Kh + g);
            cp16(sb + TKV + d, Vh + g);
        }
    };

    float m0r = -1e30f, m1r = -1e30f, l0r = 0.f, l1r = 0.f;
    float accO[8][4];
#pragma unroll
    for (int i = 0; i < 8; i++)
#pragma unroll
        for (int j = 0; j < 4; j++) accO[i][j] = 0.f;

    cp_kv(0, 0);
    asm volatile("cp.async.commit_group;");

    for (int t = 0; t < 8; t++) {
        __syncthreads();
        if (t < 7) {
            cp_kv((t + 1) & 1, t + 1);
            asm volatile("cp.async.commit_group;");
            asm volatile("cp.async.wait_group 1;");
        } else {
            asm volatile("cp.async.wait_group 0;");
        }
        __syncthreads();

        const uint32_t kvb = smu + OFF_KV + (t & 1) * STAGE_KV;

        // ---- S = Q K^T (2-pass fp16, pass-major) ----
        float s[8][4];
#pragma unroll
        for (int i = 0; i < 8; i++)
#pragma unroll
            for (int j = 0; j < 4; j++) s[i][j] = 0.f;

#pragma unroll
        for (int ks = 0; ks < 4; ks++) {
            const uint32_t kso = ks * 32;
            uint32_t ah[4], al[4], bh[8][2];
            {
                uint32_t qa = smu + warp * (16 * QST * 2) + patA + kso;
                LDSM4(ah[0], ah[1], ah[2], ah[3], qa);
                LDSM4(al[0], al[1], al[2], al[3], qa + QTILE);
            }
#pragma unroll
            for (int p = 0; p < 4; p++) {
                uint32_t kd = kvb + p * (16 * QST * 2) + patB + kso;
                LDSM4(bh[2*p][0], bh[2*p][1], bh[2*p+1][0], bh[2*p+1][1], kd);
            }
#pragma unroll
            for (int ni = 0; ni < 8; ni++) MMA_F16(s[ni], ah, bh[ni]);
#pragma unroll
            for (int ni = 0; ni < 8; ni++) MMA_F16(s[ni], al, bh[ni]);
        }

        // ---- mask (from L2) + online softmax ----
        const int grow = warp * 16 + frow;
        uint2 a0 = *(const uint2*)&adjbits[(size_t)(q0 + grow) * 16 + t * 2];
        uint2 a1 = *(const uint2*)&adjbits[(size_t)(q0 + grow + 8) * 16 + t * 2];
        uint32_t w0p[2] = {a0.x, a0.y};
        uint32_t w1p[2] = {a1.x, a1.y};
        float mx0 = -1e30f, mx1 = -1e30f;
#pragma unroll
        for (int ni = 0; ni < 8; ni++) {
            int col = ni * 8 + fcol;
            uint32_t w0 = w0p[ni >> 2], w1 = w1p[ni >> 2];
            if (!((w0 >> (col & 31)) & 1u))       s[ni][0] = -1e30f;
            if (!((w0 >> ((col + 1) & 31)) & 1u)) s[ni][1] = -1e30f;
            if (!((w1 >> (col & 31)) & 1u))       s[ni][2] = -1e30f;
            if (!((w1 >> ((col + 1) & 31)) & 1u)) s[ni][3] = -1e30f;
            mx0 = fmaxf(mx0, fmaxf(s[ni][0], s[ni][1]));
            mx1 = fmaxf(mx1, fmaxf(s[ni][2], s[ni][3]));
        }
        mx0 = fmaxf(mx0, __shfl_xor_sync(0xffffffffu, mx0, 1));
        mx0 = fmaxf(mx0, __shfl_xor_sync(0xffffffffu, mx0, 2));
        mx1 = fmaxf(mx1, __shfl_xor_sync(0xffffffffu, mx1, 1));
        mx1 = fmaxf(mx1, __shfl_xor_sync(0xffffffffu, mx1, 2));
        float mn0 = fmaxf(m0r, mx0), mn1 = fmaxf(m1r, mx1);
        float sc0 = __expf(m0r - mn0), sc1 = __expf(m1r - mn1);
        float ts0 = 0.f, ts1 = 0.f;
#pragma unroll
        for (int ni = 0; ni < 8; ni++) {
            s[ni][0] = __expf(s[ni][0] - mn0);
            s[ni][1] = __expf(s[ni][1] - mn0);
            s[ni][2] = __expf(s[ni][2] - mn1);
            s[ni][3] = __expf(s[ni][3] - mn1);
            ts0 += s[ni][0] + s[ni][1];
            ts1 += s[ni][2] + s[ni][3];
        }
        ts0 += __shfl_xor_sync(0xffffffffu, ts0, 1);
        ts0 += __shfl_xor_sync(0xffffffffu, ts0, 2);
        ts1 += __shfl_xor_sync(0xffffffffu, ts1, 1);
        ts1 += __shfl_xor_sync(0xffffffffu, ts1, 2);
        l0r = l0r * sc0 + ts0;  l1r = l1r * sc1 + ts1;
        m0r = mn0;  m1r = mn1;
#pragma unroll
        for (int ni = 0; ni < 8; ni++) {
            accO[ni][0] *= sc0; accO[ni][1] *= sc0;
            accO[ni][2] *= sc1; accO[ni][3] *= sc1;
        }

        // ---- O += P V (2-pass: P split fp16 in regs, V single fp16) ----
#pragma unroll
        for (int kt = 0; kt < 4; kt++) {
            uint32_t pah[4], pal[4];
            pah[0] = f2h2(s[2*kt][1],   s[2*kt][0]);
            pal[0] = f2h2(s[2*kt][1]   - h_hi(pah[0]), s[2*kt][0]   - h_lo(pah[0]));
            pah[1] = f2h2(s[2*kt][3],   s[2*kt][2]);
            pal[1] = f2h2(s[2*kt][3]   - h_hi(pah[1]), s[2*kt][2]   - h_lo(pah[1]));
            pah[2] = f2h2(s[2*kt+1][1], s[2*kt+1][0]);
            pal[2] = f2h2(s[2*kt+1][1] - h_hi(pah[2]), s[2*kt+1][0] - h_lo(pah[2]));
            pah[3] = f2h2(s[2*kt+1][3], s[2*kt+1][2]);
            pal[3] = f2h2(s[2*kt+1][3] - h_hi(pah[3]), s[2*kt+1][2] - h_lo(pah[3]));
            uint32_t vh[8][2];
#pragma unroll
            for (int p = 0; p < 4; p++) {
                uint32_t vd = kvb + TKV + kt * (16 * QST * 2) + patA + p * 32;
                LDSM4T(vh[2*p][0], vh[2*p][1], vh[2*p+1][0], vh[2*p+1][1], vd);
            }
#pragma unroll
            for (int d = 0; d < 8; d++) MMA_F16(accO[d], pah, vh[d]);
#pragma unroll
            for (int d = 0; d < 8; d++) MMA_F16(accO[d], pal, vh[d]);
        }
    }

    float i0 = 1.f / l0r, i1 = 1.f / l1r;
    const size_t obase = rbase * DMODEL;
    const int growg = q0 + warp * 16 + frow;
#pragma unroll
    for (int ni = 0; ni < 8; ni++) {
        int col = hc + ni * 8 + fcol;
        float o00 = accO[ni][0] * i0, o01 = accO[ni][1] * i0;
        float o10 = accO[ni][2] * i1, o11 = accO[ni][3] * i1;
        uint32_t hh0 = f2h2(o01, o00);
        uint32_t ll0 = f2h2(o01 - h_hi(hh0), o00 - h_lo(hh0));
        uint32_t hh1 = f2h2(o11, o10);
        uint32_t ll1 = f2h2(o11 - h_hi(hh1), o10 - h_lo(hh1));
        *(uint32_t*)&Oh[obase + (size_t)growg * DMODEL + col] = hh0;
        *(uint32_t*)&Ol[obase + (size_t)growg * DMODEL + col] = ll0;
        *(uint32_t*)&Oh[obase + (size_t)(growg + 8) * DMODEL + col] = hh1;
        *(uint32_t*)&Ol[obase + (size_t)(growg + 8) * DMODEL + col] = ll1;
    }
}

// ---------------- launch -----------------------------------------------------
extern "C" void kernel_launch(void* const* d_in, const int* in_sizes, int n_in,
                              void* d_out, int out_size)
{
    const float* x  = (const float*)d_in[0];
    const int*   adj = (const int*) d_in[1];
    const float* wq = (const float*)d_in[2];
    const float* bq = (const float*)d_in[3];
    const float* wk = (const float*)d_in[4];
    const float* bk = (const float*)d_in[5];
    const float* wv = (const float*)d_in[6];
    const float* bv = (const float*)d_in[7];
    const float* wo = (const float*)d_in[8];
    const float* bo = (const float*)d_in[9];
    float* out = (float*)d_out;

    float* gQf;
    __half *gkh, *gvh, *gxh, *gxl, *gah, *gal, *gwh;
    uint32_t* gab;
    cudaGetSymbolAddress((void**)&gQf, g_Qf);
    cudaGetSymbolAddress((void**)&gkh, g_kh);
    cudaGetSymbolAddress((void**)&gvh, g_vh);
    cudaGetSymbolAddress((void**)&gxh, g_xh);
    cudaGetSymbolAddress((void**)&gxl, g_xl);
    cudaGetSymbolAddress((void**)&gah, g_ah);
    cudaGetSymbolAddress((void**)&gal, g_al);
    cudaGetSymbolAddress((void**)&gwh, g_wh);
    cudaGetSymbolAddress((void**)&gab, g_adjbits);

    cudaFuncSetAttribute(mma_gemm,
                         cudaFuncAttributeMaxDynamicSharedMemorySize, PIPE32);
    cudaFuncSetAttribute(attn_mma,
                         cudaFuncAttributeMaxDynamicSharedMemorySize, ATTN4_SMEM);

    const int WSZ = DMODEL * DMODEL;           // 65536
    const int n4x = MTOT * DMODEL / 4;         // 2097152

    split_kernel<<<n4x / 256, 256>>>(x, gxh, gxl, n4x);
    split_w<<<dim3(WSZ / 4 / 256, 4), 256>>>(wq, wk, wv, wo, gwh);
    pack_adj<<<SEQ * (SEQ/32) / 256, 256>>>(adj, gab);

    // fused QKV projection: Q (fp32, pre-scaled) + K,V (single fp16)
    mma_gemm<<<dim3(DQKV / 128, MTOT / 128), 256, PIPE32>>>(
        gxh, gxl, gwh, bq, bk, bv, gQf, gkh, gvh, 1);

    attn_mma<<<dim3(SEQ / 128, NHEAD, BATCH), 256, ATTN4_SMEM>>>(
        gQf, gkh, gvh, gab, gah, gal);

    mma_gemm<<<dim3(DMODEL / 128, MTOT / 128), 256, PIPE32>>>(
        gah, gal, gwh + 3*WSZ, bo, bo, bo, out, gkh, gvh, 0);
}